// round 10
// baseline (speedup 1.0000x reference)
#include <cuda_runtime.h>
#include <cuda_bf16.h>
#include <cuda_fp16.h>
#include <cstdint>

// Problem-fixed dimensions (N=100000, E=1600000, D=256, H=128, O=64)
#define NMAX 100000
#define EMAX 1600000
#define DDIM 256
#define HDIM 128
#define ODIM 64

// ============================ warp-MMA helpers (plain sm_103 PTX) ============================
__device__ __forceinline__ uint32_t smem_to_u32(const void* p) {
    uint32_t a;
    asm("{ .reg .u64 t; cvta.to.shared.u64 t, %1; cvt.u32.u64 %0, t; }" : "=r"(a) : "l"(p));
    return a;
}
__device__ __forceinline__ void ldmx4(uint32_t* r, uint32_t addr) {
    asm volatile("ldmatrix.sync.aligned.m8n8.x4.shared.b16 {%0,%1,%2,%3}, [%4];"
        : "=r"(r[0]), "=r"(r[1]), "=r"(r[2]), "=r"(r[3]) : "r"(addr));
}
__device__ __forceinline__ void mma16816(float* d, const uint32_t* a, const uint32_t* b) {
    asm volatile("mma.sync.aligned.m16n8k16.row.col.f32.bf16.bf16.f32 "
        "{%0,%1,%2,%3}, {%4,%5,%6,%7}, {%8,%9}, {%0,%1,%2,%3};"
        : "+f"(d[0]), "+f"(d[1]), "+f"(d[2]), "+f"(d[3])
        : "r"(a[0]), "r"(a[1]), "r"(a[2]), "r"(a[3]), "r"(b[0]), "r"(b[1]));
}
__device__ __forceinline__ uint32_t bpack(__nv_bfloat16 a, __nv_bfloat16 b) {
    __nv_bfloat162 t = __halves2bfloat162(a, b);
    return *reinterpret_cast<uint32_t*>(&t);
}

// ---------------- device scratch (static, no allocation) ----------------
__device__ float  g_h1[NMAX*HDIM];                 // x @ W1 (fp32)
__device__ float  g_g1[NMAX*HDIM];                 // relu(agg_gcn(h1)+b1) fp32
__device__ float  g_p1[NMAX*HDIM];                 // relu(agg_ppmi(h1)+b1) fp32
__device__ __half g_h2[NMAX*2*ODIM];               // interleaved fp16: [node][0:64)=g, [64:128)=p
__device__ __nv_bfloat16 g_w1h[HDIM*DDIM];         // W1^T splits: [n=128][k=256]
__device__ __nv_bfloat16 g_w1l[HDIM*DDIM];
__device__ __nv_bfloat16 g_w2h[ODIM*HDIM];         // W2^T splits: [n=64][k=128]
__device__ __nv_bfloat16 g_w2l[ODIM*HDIM];
__device__ float g_disg[NMAX];
__device__ float g_disp[NMAX];
__device__ int   g_cnt   [NMAX];
__device__ int   g_cursor[NMAX];
__device__ int   g_colptr[NMAX+1];
__device__ int   g_src[EMAX];
__device__ float g_gn [EMAX];
__device__ float g_pn [EMAX];
__device__ int   g_bsums[128];

// ---------------- static stream/event fork (created at load; falls back to serial) ----------
static cudaStream_t g_s2 = nullptr;
static cudaEvent_t  g_ev0 = nullptr, g_ev1 = nullptr;
namespace {
struct ForkInit {
    ForkInit() {
        if (cudaStreamCreateWithFlags(&g_s2, cudaStreamNonBlocking) != cudaSuccess) g_s2 = nullptr;
        if (cudaEventCreateWithFlags(&g_ev0, cudaEventDisableTiming) != cudaSuccess) g_ev0 = nullptr;
        if (cudaEventCreateWithFlags(&g_ev1, cudaEventDisableTiming) != cudaSuccess) g_ev1 = nullptr;
    }
};
ForkInit g_forkinit;
}

// ---------------- graph build (re-run every replay) ----------------
__global__ void k_init(int n) {
    int i = blockIdx.x * blockDim.x + threadIdx.x;
    if (i < n) { g_cnt[i] = 0; g_cursor[i] = 0; g_disg[i] = 1.0f; g_disp[i] = 1.0f; }
}

__global__ void k_deg(const int* __restrict__ ei, const float* __restrict__ ppmi, int E) {
    int e = blockIdx.x * blockDim.x + threadIdx.x;
    if (e < E) {
        int r = ei[e]; int c = ei[E + e];
        atomicAdd(&g_disg[r], 1.0f);
        atomicAdd(&g_disp[r], ppmi[e]);
        atomicAdd(&g_cnt[c], 1);
    }
}

__global__ void k_rsqrt(int n) {
    int i = blockIdx.x * blockDim.x + threadIdx.x;
    if (i < n) { g_disg[i] = rsqrtf(g_disg[i]); g_disp[i] = rsqrtf(g_disp[i]); }
}

__global__ void k_scan1(int n) {
    __shared__ int wsum[32];
    int i = blockIdx.x * 1024 + threadIdx.x;
    int v = (i < n) ? g_cnt[i] : 0;
    int x = v;
    #pragma unroll
    for (int o = 1; o < 32; o <<= 1) {
        int y = __shfl_up_sync(0xffffffffu, x, o);
        if ((threadIdx.x & 31) >= o) x += y;
    }
    if ((threadIdx.x & 31) == 31) wsum[threadIdx.x >> 5] = x;
    __syncthreads();
    if (threadIdx.x < 32) {
        int s = wsum[threadIdx.x];
        #pragma unroll
        for (int o = 1; o < 32; o <<= 1) {
            int y = __shfl_up_sync(0xffffffffu, s, o);
            if (threadIdx.x >= o) s += y;
        }
        wsum[threadIdx.x] = s;
    }
    __syncthreads();
    int base = (threadIdx.x >= 32) ? wsum[(threadIdx.x >> 5) - 1] : 0;
    int incl = base + x;
    if (i < n) g_colptr[i] = incl - v;
    if (threadIdx.x == 1023) g_bsums[blockIdx.x] = incl;
}

__global__ void k_scan2(int nb) {
    __shared__ int s[128];
    int t = threadIdx.x;
    s[t] = (t < nb) ? g_bsums[t] : 0;
    __syncthreads();
    for (int o = 1; o < 128; o <<= 1) {
        int y = (t >= o) ? s[t - o] : 0;
        __syncthreads();
        s[t] += y;
        __syncthreads();
    }
    if (t < nb) g_bsums[t] = (t > 0) ? s[t - 1] : 0;
}

__global__ void k_scan3(int n, int E) {
    int i = blockIdx.x * 1024 + threadIdx.x;
    if (i < n) g_colptr[i] += g_bsums[blockIdx.x];
    if (i == 0) g_colptr[n] = E;
}

__global__ void k_fill(const int* __restrict__ ei, const float* __restrict__ ppmi, int E) {
    int e = blockIdx.x * blockDim.x + threadIdx.x;
    if (e >= E) return;
    int r = ei[e]; int c = ei[E + e];
    int pos = g_colptr[c] + atomicAdd(&g_cursor[c], 1);
    g_src[pos] = r;
    g_gn[pos] = g_disg[r] * g_disg[c];
    g_pn[pos] = g_disp[r] * ppmi[e] * g_disp[c];
}

// ---------------- weight split prep: both W1 and W2 in one launch ----------------
__global__ void k_splitW(const float* __restrict__ W1, const float* __restrict__ W2) {
    int i = blockIdx.x * blockDim.x + threadIdx.x;
    if (i < DDIM * HDIM) {                       // W1 [256,128] -> T splits [128][256]
        int k = i >> 7, nn = i & 127;
        float v = W1[k * HDIM + nn];
        __nv_bfloat16 h = __float2bfloat16(v);
        g_w1h[nn * DDIM + k] = h;
        g_w1l[nn * DDIM + k] = __float2bfloat16(v - __bfloat162float(h));
    } else if (i < DDIM * HDIM + HDIM * ODIM) {  // W2 [128,64] -> T splits [64][128]
        int j = i - DDIM * HDIM;
        int k = j >> 6, nn = j & 63;
        float v = W2[k * ODIM + nn];
        __nv_bfloat16 h = __float2bfloat16(v);
        g_w2h[nn * HDIM + k] = h;
        g_w2l[nn * HDIM + k] = __float2bfloat16(v - __bfloat162float(h));
    }
}

// ---------------- GEMM1: h1[M,128] = x[M,256] @ W1 via bf16x3 mma.sync, reg-prefetch ----------
static constexpr int G1_SMEM = 4 * 18432;   // Ahi/Alo/Bhi/Blo, 128 rows x 144B
__global__ void __launch_bounds__(256, 1) k_gemm1_tc(const float* __restrict__ x, int M) {
    extern __shared__ char smem[];
    uint32_t sb = smem_to_u32(smem);
    const int tid = threadIdx.x, wid = tid >> 5, lane = tid & 31;
    const int warpM = wid & 3, warpN = wid >> 2;          // 4 x 2 warps
    const int AHI = 0, ALO = 18432, BHI = 36864, BLO = 55296;

    long long row0 = (long long)blockIdx.x * 128;
    int nvalid = (int)((M - row0 < 128) ? (M - row0) : 128);
    const float4* x4 = reinterpret_cast<const float4*>(x);
    const uint4* wh = reinterpret_cast<const uint4*>(g_w1h);
    const uint4* wl = reinterpret_cast<const uint4*>(g_w1l);

    float acc[2][8][4];
    #pragma unroll
    for (int i = 0; i < 2; i++)
        #pragma unroll
        for (int j = 0; j < 8; j++)
            #pragma unroll
            for (int k = 0; k < 4; k++) acc[i][j][k] = 0.0f;

    const int a_r = (lane & 7) + ((lane & 8) ? 8 : 0);
    const int a_c = (lane & 16) ? 8 : 0;
    const int b_r = (lane & 7) + ((lane & 16) ? 8 : 0);
    const int b_c = (lane & 8) ? 8 : 0;

    float4 aR[8];          // prefetch regs: A (fp32, converted at store)
    uint4  bhR[4], blR[4]; // prefetch regs: B hi/lo

    // chunk loader: A rows 128 x 16 float4 (64 cols), B 128 x 8 uint4
    auto load_chunk = [&](int c) {
        int k0f = c * 16, k0u = c * 8;
        #pragma unroll
        for (int i = 0; i < 8; i++) {
            int u = tid + i * 256;
            int r = u >> 4, cc = u & 15;
            aR[i] = (r < nvalid) ? x4[(size_t)(row0 + r) * 64 + k0f + cc]
                                 : make_float4(0, 0, 0, 0);
        }
        #pragma unroll
        for (int i = 0; i < 4; i++) {
            int u = tid + i * 256;
            int r = u >> 3, cc = u & 7;
            bhR[i] = wh[(size_t)r * 32 + k0u + cc];
            blR[i] = wl[(size_t)r * 32 + k0u + cc];
        }
    };
    auto store_chunk = [&]() {
        #pragma unroll
        for (int i = 0; i < 8; i++) {
            int u = tid + i * 256;
            int r = u >> 4, cc = u & 15;
            float4 v = aR[i];
            __nv_bfloat16 hx = __float2bfloat16(v.x), hy = __float2bfloat16(v.y);
            __nv_bfloat16 hz = __float2bfloat16(v.z), hw = __float2bfloat16(v.w);
            int bo = r * 144 + cc * 8;
            *reinterpret_cast<uint2*>(smem + AHI + bo) = make_uint2(bpack(hx, hy), bpack(hz, hw));
            *reinterpret_cast<uint2*>(smem + ALO + bo) = make_uint2(
                bpack(__float2bfloat16(v.x - __bfloat162float(hx)), __float2bfloat16(v.y - __bfloat162float(hy))),
                bpack(__float2bfloat16(v.z - __bfloat162float(hz)), __float2bfloat16(v.w - __bfloat162float(hw))));
        }
        #pragma unroll
        for (int i = 0; i < 4; i++) {
            int u = tid + i * 256;
            int r = u >> 3, cc = u & 7;
            int bo = r * 144 + cc * 16;
            *reinterpret_cast<uint4*>(smem + BHI + bo) = bhR[i];
            *reinterpret_cast<uint4*>(smem + BLO + bo) = blR[i];
        }
    };

    load_chunk(0);
    #pragma unroll 1
    for (int c = 0; c < 4; c++) {                         // K chunks of 64 (K=256)
        store_chunk();
        __syncthreads();
        if (c < 3) load_chunk(c + 1);                     // prefetch next chunk under MMA
        #pragma unroll
        for (int k16 = 0; k16 < 4; k16++) {
            int kc = k16 * 16;
            uint32_t ah[2][4], al[2][4];
            #pragma unroll
            for (int mt = 0; mt < 2; mt++) {
                uint32_t off = (uint32_t)((warpM * 32 + mt * 16 + a_r) * 144 + (kc + a_c) * 2);
                ldmx4(ah[mt], sb + AHI + off);
                ldmx4(al[mt], sb + ALO + off);
            }
            uint32_t bh[8][2], bl[8][2];
            #pragma unroll
            for (int np = 0; np < 4; np++) {
                uint32_t off = (uint32_t)((warpN * 64 + np * 16 + b_r) * 144 + (kc + b_c) * 2);
                uint32_t t4[4];
                ldmx4(t4, sb + BHI + off);
                bh[2*np][0] = t4[0]; bh[2*np][1] = t4[1];
                bh[2*np+1][0] = t4[2]; bh[2*np+1][1] = t4[3];
                ldmx4(t4, sb + BLO + off);
                bl[2*np][0] = t4[0]; bl[2*np][1] = t4[1];
                bl[2*np+1][0] = t4[2]; bl[2*np+1][1] = t4[3];
            }
            #pragma unroll
            for (int mt = 0; mt < 2; mt++)
                #pragma unroll
                for (int nt = 0; nt < 8; nt++) {
                    mma16816(acc[mt][nt], ah[mt], bh[nt]);
                    mma16816(acc[mt][nt], ah[mt], bl[nt]);
                    mma16816(acc[mt][nt], al[mt], bh[nt]);
                }
        }
        __syncthreads();
    }
    int g = lane >> 2, t = lane & 3;
    #pragma unroll
    for (int mt = 0; mt < 2; mt++) {
        long long r0 = row0 + warpM * 32 + mt * 16 + g;
        #pragma unroll
        for (int nt = 0; nt < 8; nt++) {
            int col = warpN * 64 + nt * 8 + t * 2;
            if (r0 < M)
                *reinterpret_cast<float2*>(&g_h1[r0 * HDIM + col]) =
                    make_float2(acc[mt][nt][0], acc[mt][nt][1]);
            if (r0 + 8 < M)
                *reinterpret_cast<float2*>(&g_h1[(r0 + 8) * HDIM + col]) =
                    make_float2(acc[mt][nt][2], acc[mt][nt][3]);
        }
    }
}

// ---------------- GEMM2: h2 fp16 interleaved = {g1,p1} @ W2, bf16x3, reg-prefetch ----------
static constexpr int G2_SMEM = 2 * 18432 + 2 * 9216;
__global__ void __launch_bounds__(256, 1) k_gemm2_tc(int M) {
    extern __shared__ char smem[];
    uint32_t sb = smem_to_u32(smem);
    const int tid = threadIdx.x, wid = tid >> 5, lane = tid & 31;
    const int warpM = wid & 3, warpN = wid >> 2;          // 4 x 2 warps, warp tile 32x32
    const int AHI = 0, ALO = 18432, BHI = 36864, BLO = 46080;

    long long row0 = (long long)blockIdx.x * 128;
    int nvalid = (int)((M - row0 < 128) ? (M - row0) : 128);
    const float4* a4 = reinterpret_cast<const float4*>(blockIdx.y ? g_p1 : g_g1);
    const uint4* wh = reinterpret_cast<const uint4*>(g_w2h);
    const uint4* wl = reinterpret_cast<const uint4*>(g_w2l);
    const int cbase = blockIdx.y * ODIM;

    float acc[2][4][4];
    #pragma unroll
    for (int i = 0; i < 2; i++)
        #pragma unroll
        for (int j = 0; j < 4; j++)
            #pragma unroll
            for (int k = 0; k < 4; k++) acc[i][j][k] = 0.0f;

    const int a_r = (lane & 7) + ((lane & 8) ? 8 : 0);
    const int a_c = (lane & 16) ? 8 : 0;
    const int b_r = (lane & 7) + ((lane & 16) ? 8 : 0);
    const int b_c = (lane & 8) ? 8 : 0;

    float4 aR[8];
    uint4  bhR[2], blR[2];

    auto load_chunk = [&](int c) {
        int k0f = c * 16, k0u = c * 8;
        #pragma unroll
        for (int i = 0; i < 8; i++) {
            int u = tid + i * 256;
            int r = u >> 4, cc = u & 15;
            aR[i] = (r < nvalid) ? a4[(size_t)(row0 + r) * 32 + k0f + cc]
                                 : make_float4(0, 0, 0, 0);
        }
        #pragma unroll
        for (int i = 0; i < 2; i++) {
            int u = tid + i * 256;
            int r = u >> 3, cc = u & 7;
            bhR[i] = wh[(size_t)r * 16 + k0u + cc];
            blR[i] = wl[(size_t)r * 16 + k0u + cc];
        }
    };
    auto store_chunk = [&]() {
        #pragma unroll
        for (int i = 0; i < 8; i++) {
            int u = tid + i * 256;
            int r = u >> 4, cc = u & 15;
            float4 v = aR[i];
            __nv_bfloat16 hx = __float2bfloat16(v.x), hy = __float2bfloat16(v.y);
            __nv_bfloat16 hz = __float2bfloat16(v.z), hw = __float2bfloat16(v.w);
            int bo = r * 144 + cc * 8;
            *reinterpret_cast<uint2*>(smem + AHI + bo) = make_uint2(bpack(hx, hy), bpack(hz, hw));
            *reinterpret_cast<uint2*>(smem + ALO + bo) = make_uint2(
                bpack(__float2bfloat16(v.x - __bfloat162float(hx)), __float2bfloat16(v.y - __bfloat162float(hy))),
                bpack(__float2bfloat16(v.z - __bfloat162float(hz)), __float2bfloat16(v.w - __bfloat162float(hw))));
        }
        #pragma unroll
        for (int i = 0; i < 2; i++) {
            int u = tid + i * 256;
            int r = u >> 3, cc = u & 7;
            int bo = r * 144 + cc * 16;
            *reinterpret_cast<uint4*>(smem + BHI + bo) = bhR[i];
            *reinterpret_cast<uint4*>(smem + BLO + bo) = blR[i];
        }
    };

    load_chunk(0);
    #pragma unroll 1
    for (int c = 0; c < 2; c++) {                         // K chunks of 64 (K=128)
        store_chunk();
        __syncthreads();
        if (c < 1) load_chunk(c + 1);
        #pragma unroll
        for (int k16 = 0; k16 < 4; k16++) {
            int kc = k16 * 16;
            uint32_t ah[2][4], al[2][4];
            #pragma unroll
            for (int mt = 0; mt < 2; mt++) {
                uint32_t off = (uint32_t)((warpM * 32 + mt * 16 + a_r) * 144 + (kc + a_c) * 2);
                ldmx4(ah[mt], sb + AHI + off);
                ldmx4(al[mt], sb + ALO + off);
            }
            uint32_t bh[4][2], bl[4][2];
            #pragma unroll
            for (int np = 0; np < 2; np++) {
                uint32_t off = (uint32_t)((warpN * 32 + np * 16 + b_r) * 144 + (kc + b_c) * 2);
                uint32_t t4[4];
                ldmx4(t4, sb + BHI + off);
                bh[2*np][0] = t4[0]; bh[2*np][1] = t4[1];
                bh[2*np+1][0] = t4[2]; bh[2*np+1][1] = t4[3];
                ldmx4(t4, sb + BLO + off);
                bl[2*np][0] = t4[0]; bl[2*np][1] = t4[1];
                bl[2*np+1][0] = t4[2]; bl[2*np+1][1] = t4[3];
            }
            #pragma unroll
            for (int mt = 0; mt < 2; mt++)
                #pragma unroll
                for (int nt = 0; nt < 4; nt++) {
                    mma16816(acc[mt][nt], ah[mt], bh[nt]);
                    mma16816(acc[mt][nt], ah[mt], bl[nt]);
                    mma16816(acc[mt][nt], al[mt], bh[nt]);
                }
        }
        __syncthreads();
    }
    int g = lane >> 2, t = lane & 3;
    #pragma unroll
    for (int mt = 0; mt < 2; mt++) {
        long long r0 = row0 + warpM * 32 + mt * 16 + g;
        #pragma unroll
        for (int nt = 0; nt < 4; nt++) {
            int col = cbase + warpN * 32 + nt * 8 + t * 2;
            if (r0 < M)
                *reinterpret_cast<__half2*>(&g_h2[r0 * 2 * ODIM + col]) =
                    __floats2half2_rn(acc[mt][nt][0], acc[mt][nt][1]);
            if (r0 + 8 < M)
                *reinterpret_cast<__half2*>(&g_h2[(r0 + 8) * 2 * ODIM + col]) =
                    __floats2half2_rn(acc[mt][nt][2], acc[mt][nt][3]);
        }
    }
}

// ---------------- layer-1 aggregation: warp/node, both branches, fp32 out ----------------
__global__ void k_agg1(const float* __restrict__ b1, int n) {
    int node = (blockIdx.x * blockDim.x + threadIdx.x) >> 5;
    int lane = threadIdx.x & 31;
    if (node >= n) return;
    int s0 = g_colptr[node], s1 = g_colptr[node + 1];
    float4 ag = make_float4(0, 0, 0, 0);
    float4 ap = make_float4(0, 0, 0, 0);
    int e = s0;
    for (; e + 1 < s1; e += 2) {
        int sA = g_src[e], sB = g_src[e + 1];
        float gnA = g_gn[e], pnA = g_pn[e];
        float gnB = g_gn[e + 1], pnB = g_pn[e + 1];
        float4 vA = *reinterpret_cast<const float4*>(&g_h1[(size_t)sA * HDIM + lane * 4]);
        float4 vB = *reinterpret_cast<const float4*>(&g_h1[(size_t)sB * HDIM + lane * 4]);
        ag.x += gnA * vA.x + gnB * vB.x; ag.y += gnA * vA.y + gnB * vB.y;
        ag.z += gnA * vA.z + gnB * vB.z; ag.w += gnA * vA.w + gnB * vB.w;
        ap.x += pnA * vA.x + pnB * vB.x; ap.y += pnA * vA.y + pnB * vB.y;
        ap.z += pnA * vA.z + pnB * vB.z; ap.w += pnA * vA.w + pnB * vB.w;
    }
    if (e < s1) {
        int s = g_src[e];
        float gn = g_gn[e], pn = g_pn[e];
        float4 v = *reinterpret_cast<const float4*>(&g_h1[(size_t)s * HDIM + lane * 4]);
        ag.x += gn * v.x; ag.y += gn * v.y; ag.z += gn * v.z; ag.w += gn * v.w;
        ap.x += pn * v.x; ap.y += pn * v.y; ap.z += pn * v.z; ap.w += pn * v.w;
    }
    float dg = g_disg[node]; dg *= dg;
    float dp = g_disp[node]; dp *= dp;
    float4 v = *reinterpret_cast<const float4*>(&g_h1[(size_t)node * HDIM + lane * 4]);
    ag.x += dg * v.x; ag.y += dg * v.y; ag.z += dg * v.z; ag.w += dg * v.w;
    ap.x += dp * v.x; ap.y += dp * v.y; ap.z += dp * v.z; ap.w += dp * v.w;
    float4 bb = *reinterpret_cast<const float4*>(&b1[lane * 4]);
    ag.x = fmaxf(ag.x + bb.x, 0.f); ag.y = fmaxf(ag.y + bb.y, 0.f);
    ag.z = fmaxf(ag.z + bb.z, 0.f); ag.w = fmaxf(ag.w + bb.w, 0.f);
    ap.x = fmaxf(ap.x + bb.x, 0.f); ap.y = fmaxf(ap.y + bb.y, 0.f);
    ap.z = fmaxf(ap.z + bb.z, 0.f); ap.w = fmaxf(ap.w + bb.w, 0.f);
    size_t base = (size_t)node * HDIM + lane * 4;
    *reinterpret_cast<float4*>(&g_g1[base]) = ag;
    *reinterpret_cast<float4*>(&g_p1[base]) = ap;
}

// ---------------- layer-2 aggregation (fp16 gather) + attention combine ----------------
// lanes 0-15: GCN branch (h2 cols 0-63), lanes 16-31: PPMI branch (cols 64-127)
__device__ __forceinline__ void h2gather(size_t node, int lane, float4& a, float w) {
    uint2 u = *reinterpret_cast<const uint2*>(&g_h2[node * 2 * ODIM + lane * 4]);
    float2 f01 = __half22float2(*reinterpret_cast<__half2*>(&u.x));
    float2 f23 = __half22float2(*reinterpret_cast<__half2*>(&u.y));
    a.x += w * f01.x; a.y += w * f01.y; a.z += w * f23.x; a.w += w * f23.y;
}

__global__ void k_agg2_combine(const float* __restrict__ b2,
                               const float* __restrict__ dw,
                               const float* __restrict__ db,
                               float* __restrict__ out, int n) {
    int node = (blockIdx.x * blockDim.x + threadIdx.x) >> 5;
    int lane = threadIdx.x & 31;
    if (node >= n) return;
    int s0 = g_colptr[node], s1 = g_colptr[node + 1];
    const bool isg = lane < 16;
    float4 a = make_float4(0, 0, 0, 0);
    int e = s0;
    for (; e + 1 < s1; e += 2) {
        int sA = g_src[e], sB = g_src[e + 1];
        float wA = isg ? g_gn[e] : g_pn[e];
        float wB = isg ? g_gn[e + 1] : g_pn[e + 1];
        h2gather((size_t)sA, lane, a, wA);
        h2gather((size_t)sB, lane, a, wB);
    }
    if (e < s1) {
        int s = g_src[e];
        h2gather((size_t)s, lane, a, isg ? g_gn[e] : g_pn[e]);
    }
    float d = isg ? g_disg[node] : g_disp[node];
    d *= d;
    h2gather((size_t)node, lane, a, d);
    int c4 = (lane & 15) * 4;
    float4 bb = *reinterpret_cast<const float4*>(&b2[c4]);
    a.x += bb.x; a.y += bb.y; a.z += bb.z; a.w += bb.w;
    // per-branch logits via masked full-warp reduction
    float4 w4 = *reinterpret_cast<const float4*>(&dw[c4]);
    float dot = a.x * w4.x + a.y * w4.y + a.z * w4.z + a.w * w4.w;
    float pg = isg ? dot : 0.0f;
    float pp = isg ? 0.0f : dot;
    #pragma unroll
    for (int o = 16; o; o >>= 1) {
        pg += __shfl_xor_sync(0xffffffffu, pg, o);
        pp += __shfl_xor_sync(0xffffffffu, pp, o);
    }
    float bd = db[0];
    float lg = pg + bd, lp = pp + bd;
    float m = fmaxf(lg, lp);
    float eg = __expf(lg - m), ep = __expf(lp - m);
    float wg = eg / (eg + ep), wp = 1.0f - wg;
    float4 o4;
    o4.x = __shfl_xor_sync(0xffffffffu, a.x, 16);
    o4.y = __shfl_xor_sync(0xffffffffu, a.y, 16);
    o4.z = __shfl_xor_sync(0xffffffffu, a.z, 16);
    o4.w = __shfl_xor_sync(0xffffffffu, a.w, 16);
    if (isg) {
        float4 r;
        r.x = wg * a.x + wp * o4.x; r.y = wg * a.y + wp * o4.y;
        r.z = wg * a.z + wp * o4.z; r.w = wg * a.w + wp * o4.w;
        *reinterpret_cast<float4*>(&out[(size_t)node * ODIM + c4]) = r;
    }
}

// ---------------- launch ----------------
extern "C" void kernel_launch(void* const* d_in, const int* in_sizes, int n_in,
                              void* d_out, int out_size) {
    const float* x    = (const float*)d_in[0];
    const int*   ei   = (const int*)d_in[1];     // int32 [2, E]
    const float* ppmi = (const float*)d_in[2];
    const float* W1   = (const float*)d_in[3];
    const float* b1   = (const float*)d_in[4];
    const float* W2   = (const float*)d_in[5];
    const float* b2   = (const float*)d_in[6];
    const float* dw   = (const float*)d_in[7];
    const float* db   = (const float*)d_in[8];
    float*       out  = (float*)d_out;

    const int N = in_sizes[0] / DDIM;
    const int E = in_sizes[2];

    cudaFuncSetAttribute(k_gemm1_tc, cudaFuncAttributeMaxDynamicSharedMemorySize, G1_SMEM);
    cudaFuncSetAttribute(k_gemm2_tc, cudaFuncAttributeMaxDynamicSharedMemorySize, G2_SMEM);

    const int TB = 256;
    const bool fork = (g_s2 != nullptr) && (g_ev0 != nullptr) && (g_ev1 != nullptr);
    cudaStream_t sb = fork ? g_s2 : (cudaStream_t)0;

    // --- branch A (side stream): CSR graph build ---
    if (fork) {
        cudaEventRecord(g_ev0, 0);
        cudaStreamWaitEvent(g_s2, g_ev0, 0);
    }
    k_init<<<(N + TB - 1) / TB, TB, 0, sb>>>(N);
    k_deg<<<(E + TB - 1) / TB, TB, 0, sb>>>(ei, ppmi, E);
    k_rsqrt<<<(N + TB - 1) / TB, TB, 0, sb>>>(N);
    int nb = (N + 1023) / 1024;
    k_scan1<<<nb, 1024, 0, sb>>>(N);
    k_scan2<<<1, 128, 0, sb>>>(nb);
    k_scan3<<<nb, 1024, 0, sb>>>(N, E);
    k_fill<<<(E + TB - 1) / TB, TB, 0, sb>>>(ei, ppmi, E);
    if (fork) cudaEventRecord(g_ev1, g_s2);

    // --- branch B (capture stream): weight splits + GEMM1 ---
    k_splitW<<<(DDIM * HDIM + HDIM * ODIM + TB - 1) / TB, TB>>>(W1, W2);
    int g1 = (N + 127) / 128;
    k_gemm1_tc<<<g1, 256, G1_SMEM>>>(x, N);

    // --- join, then serial tail ---
    if (fork) cudaStreamWaitEvent((cudaStream_t)0, g_ev1, 0);
    k_agg1<<<(N * 32 + TB - 1) / TB, TB>>>(b1, N);
    dim3 grid2(g1, 2);
    k_gemm2_tc<<<grid2, 256, G2_SMEM>>>(N);
    k_agg2_combine<<<(N * 32 + TB - 1) / TB, TB>>>(b2, dw, db, out, N);
}

// round 11
// speedup vs baseline: 1.2716x; 1.2716x over previous
#include <cuda_runtime.h>
#include <cuda_bf16.h>
#include <cuda_fp16.h>
#include <cstdint>

// Problem-fixed dimensions (N=100000, E=1600000, D=256, H=128, O=64)
#define NMAX 100000
#define EMAX 1600000
#define DDIM 256
#define HDIM 128
#define ODIM 64

// ============================ warp-MMA helpers (plain sm_103 PTX) ============================
__device__ __forceinline__ uint32_t smem_to_u32(const void* p) {
    uint32_t a;
    asm("{ .reg .u64 t; cvta.to.shared.u64 t, %1; cvt.u32.u64 %0, t; }" : "=r"(a) : "l"(p));
    return a;
}
__device__ __forceinline__ void ldmx4(uint32_t* r, uint32_t addr) {
    asm volatile("ldmatrix.sync.aligned.m8n8.x4.shared.b16 {%0,%1,%2,%3}, [%4];"
        : "=r"(r[0]), "=r"(r[1]), "=r"(r[2]), "=r"(r[3]) : "r"(addr));
}
__device__ __forceinline__ void mma16816(float* d, const uint32_t* a, const uint32_t* b) {
    asm volatile("mma.sync.aligned.m16n8k16.row.col.f32.bf16.bf16.f32 "
        "{%0,%1,%2,%3}, {%4,%5,%6,%7}, {%8,%9}, {%0,%1,%2,%3};"
        : "+f"(d[0]), "+f"(d[1]), "+f"(d[2]), "+f"(d[3])
        : "r"(a[0]), "r"(a[1]), "r"(a[2]), "r"(a[3]), "r"(b[0]), "r"(b[1]));
}
__device__ __forceinline__ uint32_t bpack(__nv_bfloat16 a, __nv_bfloat16 b) {
    __nv_bfloat162 t = __halves2bfloat162(a, b);
    return *reinterpret_cast<uint32_t*>(&t);
}

// ---------------- device scratch (static, no allocation) ----------------
__device__ float  g_h1[NMAX*HDIM];                 // x @ W1 (fp32)
__device__ float  g_g1[NMAX*HDIM];                 // relu(agg_gcn(h1)+b1) fp32
__device__ float  g_p1[NMAX*HDIM];                 // relu(agg_ppmi(h1)+b1) fp32
__device__ __half g_h2[NMAX*2*ODIM];               // interleaved fp16: [node][0:64)=g, [64:128)=p
__device__ __nv_bfloat16 g_w1h[HDIM*DDIM];         // W1^T splits: [n=128][k=256]
__device__ __nv_bfloat16 g_w1l[HDIM*DDIM];
__device__ __nv_bfloat16 g_w2h[ODIM*HDIM];         // W2^T splits: [n=64][k=128]
__device__ __nv_bfloat16 g_w2l[ODIM*HDIM];
__device__ float g_disg[NMAX];
__device__ float g_disp[NMAX];
__device__ int   g_cnt   [NMAX];
__device__ int   g_cursor[NMAX];
__device__ int   g_colptr[NMAX+1];
__device__ int   g_src[EMAX];
__device__ float g_gn [EMAX];
__device__ float g_pn [EMAX];
__device__ int   g_bsums[128];

// ---------------- static stream/event fork (created at load; falls back to serial) ----------
static cudaStream_t g_s2 = nullptr;
static cudaEvent_t  g_ev0 = nullptr, g_ev1 = nullptr;
namespace {
struct ForkInit {
    ForkInit() {
        if (cudaStreamCreateWithFlags(&g_s2, cudaStreamNonBlocking) != cudaSuccess) g_s2 = nullptr;
        if (cudaEventCreateWithFlags(&g_ev0, cudaEventDisableTiming) != cudaSuccess) g_ev0 = nullptr;
        if (cudaEventCreateWithFlags(&g_ev1, cudaEventDisableTiming) != cudaSuccess) g_ev1 = nullptr;
    }
};
ForkInit g_forkinit;
}

// ---------------- graph build (re-run every replay) ----------------
__global__ void k_init(int n) {
    int i = blockIdx.x * blockDim.x + threadIdx.x;
    if (i < n) { g_cnt[i] = 0; g_cursor[i] = 0; g_disg[i] = 1.0f; g_disp[i] = 1.0f; }
}

__global__ void k_deg(const int* __restrict__ ei, const float* __restrict__ ppmi, int E) {
    int e = blockIdx.x * blockDim.x + threadIdx.x;
    if (e < E) {
        int r = ei[e]; int c = ei[E + e];
        atomicAdd(&g_disg[r], 1.0f);
        atomicAdd(&g_disp[r], ppmi[e]);
        atomicAdd(&g_cnt[c], 1);
    }
}

__global__ void k_rsqrt(int n) {
    int i = blockIdx.x * blockDim.x + threadIdx.x;
    if (i < n) { g_disg[i] = rsqrtf(g_disg[i]); g_disp[i] = rsqrtf(g_disp[i]); }
}

__global__ void k_scan1(int n) {
    __shared__ int wsum[32];
    int i = blockIdx.x * 1024 + threadIdx.x;
    int v = (i < n) ? g_cnt[i] : 0;
    int x = v;
    #pragma unroll
    for (int o = 1; o < 32; o <<= 1) {
        int y = __shfl_up_sync(0xffffffffu, x, o);
        if ((threadIdx.x & 31) >= o) x += y;
    }
    if ((threadIdx.x & 31) == 31) wsum[threadIdx.x >> 5] = x;
    __syncthreads();
    if (threadIdx.x < 32) {
        int s = wsum[threadIdx.x];
        #pragma unroll
        for (int o = 1; o < 32; o <<= 1) {
            int y = __shfl_up_sync(0xffffffffu, s, o);
            if (threadIdx.x >= o) s += y;
        }
        wsum[threadIdx.x] = s;
    }
    __syncthreads();
    int base = (threadIdx.x >= 32) ? wsum[(threadIdx.x >> 5) - 1] : 0;
    int incl = base + x;
    if (i < n) g_colptr[i] = incl - v;
    if (threadIdx.x == 1023) g_bsums[blockIdx.x] = incl;
}

__global__ void k_scan2(int nb) {
    __shared__ int s[128];
    int t = threadIdx.x;
    s[t] = (t < nb) ? g_bsums[t] : 0;
    __syncthreads();
    for (int o = 1; o < 128; o <<= 1) {
        int y = (t >= o) ? s[t - o] : 0;
        __syncthreads();
        s[t] += y;
        __syncthreads();
    }
    if (t < nb) g_bsums[t] = (t > 0) ? s[t - 1] : 0;
}

__global__ void k_scan3(int n, int E) {
    int i = blockIdx.x * 1024 + threadIdx.x;
    if (i < n) g_colptr[i] += g_bsums[blockIdx.x];
    if (i == 0) g_colptr[n] = E;
}

__global__ void k_fill(const int* __restrict__ ei, const float* __restrict__ ppmi, int E) {
    int e = blockIdx.x * blockDim.x + threadIdx.x;
    if (e >= E) return;
    int r = ei[e]; int c = ei[E + e];
    int pos = g_colptr[c] + atomicAdd(&g_cursor[c], 1);
    g_src[pos] = r;
    g_gn[pos] = g_disg[r] * g_disg[c];
    g_pn[pos] = g_disp[r] * ppmi[e] * g_disp[c];
}

// ---------------- weight split prep: both W1 and W2 in one launch ----------------
__global__ void k_splitW(const float* __restrict__ W1, const float* __restrict__ W2) {
    int i = blockIdx.x * blockDim.x + threadIdx.x;
    if (i < DDIM * HDIM) {                       // W1 [256,128] -> T splits [128][256]
        int k = i >> 7, nn = i & 127;
        float v = W1[k * HDIM + nn];
        __nv_bfloat16 h = __float2bfloat16(v);
        g_w1h[nn * DDIM + k] = h;
        g_w1l[nn * DDIM + k] = __float2bfloat16(v - __bfloat162float(h));
    } else if (i < DDIM * HDIM + HDIM * ODIM) {  // W2 [128,64] -> T splits [64][128]
        int j = i - DDIM * HDIM;
        int k = j >> 6, nn = j & 63;
        float v = W2[k * ODIM + nn];
        __nv_bfloat16 h = __float2bfloat16(v);
        g_w2h[nn * HDIM + k] = h;
        g_w2l[nn * HDIM + k] = __float2bfloat16(v - __bfloat162float(h));
    }
}

// ---------------- SMEM tile fill: ROWS x 64 bf16, padded row stride 144 B ----------------
template <int ROWS>
__device__ __forceinline__ void fill_pad(char* smem, int dst_off,
                                         const uint4* __restrict__ src,  // 8 bf16 per uint4
                                         long long first_row, int stride_u4, int k0_u4,
                                         int nvalid, int tid) {
    for (int u = tid; u < ROWS * 8; u += 256) {
        int r = u >> 3, c = u & 7;
        uint4 v = make_uint4(0, 0, 0, 0);
        if (r < nvalid) v = src[(size_t)(first_row + r) * stride_u4 + k0_u4 + c];
        *reinterpret_cast<uint4*>(smem + dst_off + r * 144 + c * 16) = v;
    }
}

// fp32 source -> hi/lo bf16 tiles in one pass (ROWS x 64 cols)
template <int ROWS>
__device__ __forceinline__ void fill_split(char* smem, int hi_off, int lo_off,
                                           const float4* __restrict__ src,  // 4 fp32 per float4
                                           long long first_row, int stride_f4, int k0_f4,
                                           int nvalid, int tid) {
    for (int u = tid; u < ROWS * 16; u += 256) {
        int r = u >> 4, c = u & 15;
        float4 v = make_float4(0, 0, 0, 0);
        if (r < nvalid) v = src[(size_t)(first_row + r) * stride_f4 + k0_f4 + c];
        __nv_bfloat16 hx = __float2bfloat16(v.x), hy = __float2bfloat16(v.y);
        __nv_bfloat16 hz = __float2bfloat16(v.z), hw = __float2bfloat16(v.w);
        uint2 hi2 = make_uint2(bpack(hx, hy), bpack(hz, hw));
        uint2 lo2 = make_uint2(
            bpack(__float2bfloat16(v.x - __bfloat162float(hx)), __float2bfloat16(v.y - __bfloat162float(hy))),
            bpack(__float2bfloat16(v.z - __bfloat162float(hz)), __float2bfloat16(v.w - __bfloat162float(hw))));
        int bo = r * 144 + c * 8;
        *reinterpret_cast<uint2*>(smem + hi_off + bo) = hi2;
        *reinterpret_cast<uint2*>(smem + lo_off + bo) = lo2;
    }
}

// ---------------- GEMM1: h1[M,128] = x[M,256] @ W1 via bf16x3 mma.sync ----------------
static constexpr int G1_SMEM = 4 * 18432;   // Ahi/Alo/Bhi/Blo, 128 rows x 144B
__global__ void __launch_bounds__(256) k_gemm1_tc(const float* __restrict__ x, int M) {
    extern __shared__ char smem[];
    uint32_t sb = smem_to_u32(smem);
    const int tid = threadIdx.x, wid = tid >> 5, lane = tid & 31;
    const int warpM = wid & 3, warpN = wid >> 2;          // 4 x 2 warps
    const int AHI = 0, ALO = 18432, BHI = 36864, BLO = 55296;

    long long row0 = (long long)blockIdx.x * 128;
    int nvalid = (int)((M - row0 < 128) ? (M - row0) : 128);
    const float4* x4 = reinterpret_cast<const float4*>(x);
    const uint4* wh = reinterpret_cast<const uint4*>(g_w1h);
    const uint4* wl = reinterpret_cast<const uint4*>(g_w1l);

    float acc[2][8][4];
    #pragma unroll
    for (int i = 0; i < 2; i++)
        #pragma unroll
        for (int j = 0; j < 8; j++)
            #pragma unroll
            for (int k = 0; k < 4; k++) acc[i][j][k] = 0.0f;

    const int a_r = (lane & 7) + ((lane & 8) ? 8 : 0);
    const int a_c = (lane & 16) ? 8 : 0;
    const int b_r = (lane & 7) + ((lane & 16) ? 8 : 0);
    const int b_c = (lane & 8) ? 8 : 0;

    #pragma unroll 1
    for (int c = 0; c < 4; c++) {                         // K chunks of 64 (K=256)
        if (c) __syncthreads();
        fill_split<128>(smem, AHI, ALO, x4, row0, 64, c * 16, nvalid, tid);
        fill_pad<128>(smem, BHI, wh, 0, 32, c * 8, 128, tid);
        fill_pad<128>(smem, BLO, wl, 0, 32, c * 8, 128, tid);
        __syncthreads();
        #pragma unroll
        for (int k16 = 0; k16 < 4; k16++) {
            int kc = k16 * 16;
            uint32_t ah[2][4], al[2][4];
            #pragma unroll
            for (int mt = 0; mt < 2; mt++) {
                uint32_t off = (uint32_t)((warpM * 32 + mt * 16 + a_r) * 144 + (kc + a_c) * 2);
                ldmx4(ah[mt], sb + AHI + off);
                ldmx4(al[mt], sb + ALO + off);
            }
            uint32_t bh[8][2], bl[8][2];
            #pragma unroll
            for (int np = 0; np < 4; np++) {
                uint32_t off = (uint32_t)((warpN * 64 + np * 16 + b_r) * 144 + (kc + b_c) * 2);
                uint32_t t4[4];
                ldmx4(t4, sb + BHI + off);
                bh[2*np][0] = t4[0]; bh[2*np][1] = t4[1];
                bh[2*np+1][0] = t4[2]; bh[2*np+1][1] = t4[3];
                ldmx4(t4, sb + BLO + off);
                bl[2*np][0] = t4[0]; bl[2*np][1] = t4[1];
                bl[2*np+1][0] = t4[2]; bl[2*np+1][1] = t4[3];
            }
            #pragma unroll
            for (int mt = 0; mt < 2; mt++)
                #pragma unroll
                for (int nt = 0; nt < 8; nt++) {
                    mma16816(acc[mt][nt], ah[mt], bh[nt]);
                    mma16816(acc[mt][nt], ah[mt], bl[nt]);
                    mma16816(acc[mt][nt], al[mt], bh[nt]);
                }
        }
    }
    int g = lane >> 2, t = lane & 3;
    #pragma unroll
    for (int mt = 0; mt < 2; mt++) {
        long long r0 = row0 + warpM * 32 + mt * 16 + g;
        #pragma unroll
        for (int nt = 0; nt < 8; nt++) {
            int col = warpN * 64 + nt * 8 + t * 2;
            if (r0 < M)
                *reinterpret_cast<float2*>(&g_h1[r0 * HDIM + col]) =
                    make_float2(acc[mt][nt][0], acc[mt][nt][1]);
            if (r0 + 8 < M)
                *reinterpret_cast<float2*>(&g_h1[(r0 + 8) * HDIM + col]) =
                    make_float2(acc[mt][nt][2], acc[mt][nt][3]);
        }
    }
}

// ---------------- GEMM2: h2 fp16 interleaved = {g1,p1} @ W2 via bf16x3 mma.sync ----------------
static constexpr int G2_SMEM = 2 * 18432 + 2 * 9216;
__global__ void __launch_bounds__(256) k_gemm2_tc(int M) {
    extern __shared__ char smem[];
    uint32_t sb = smem_to_u32(smem);
    const int tid = threadIdx.x, wid = tid >> 5, lane = tid & 31;
    const int warpM = wid & 3, warpN = wid >> 2;          // 4 x 2 warps, warp tile 32x32
    const int AHI = 0, ALO = 18432, BHI = 36864, BLO = 46080;

    long long row0 = (long long)blockIdx.x * 128;
    int nvalid = (int)((M - row0 < 128) ? (M - row0) : 128);
    const float4* a4 = reinterpret_cast<const float4*>(blockIdx.y ? g_p1 : g_g1);
    const uint4* wh = reinterpret_cast<const uint4*>(g_w2h);
    const uint4* wl = reinterpret_cast<const uint4*>(g_w2l);
    const int cbase = blockIdx.y * ODIM;

    float acc[2][4][4];
    #pragma unroll
    for (int i = 0; i < 2; i++)
        #pragma unroll
        for (int j = 0; j < 4; j++)
            #pragma unroll
            for (int k = 0; k < 4; k++) acc[i][j][k] = 0.0f;

    const int a_r = (lane & 7) + ((lane & 8) ? 8 : 0);
    const int a_c = (lane & 16) ? 8 : 0;
    const int b_r = (lane & 7) + ((lane & 16) ? 8 : 0);
    const int b_c = (lane & 8) ? 8 : 0;

    #pragma unroll 1
    for (int c = 0; c < 2; c++) {                         // K chunks of 64 (K=128)
        if (c) __syncthreads();
        fill_split<128>(smem, AHI, ALO, a4, row0, 32, c * 16, nvalid, tid);
        fill_pad<64>(smem, BHI, wh, 0, 16, c * 8, 64, tid);
        fill_pad<64>(smem, BLO, wl, 0, 16, c * 8, 64, tid);
        __syncthreads();
        #pragma unroll
        for (int k16 = 0; k16 < 4; k16++) {
            int kc = k16 * 16;
            uint32_t ah[2][4], al[2][4];
            #pragma unroll
            for (int mt = 0; mt < 2; mt++) {
                uint32_t off = (uint32_t)((warpM * 32 + mt * 16 + a_r) * 144 + (kc + a_c) * 2);
                ldmx4(ah[mt], sb + AHI + off);
                ldmx4(al[mt], sb + ALO + off);
            }
            uint32_t bh[4][2], bl[4][2];
            #pragma unroll
            for (int np = 0; np < 2; np++) {
                uint32_t off = (uint32_t)((warpN * 32 + np * 16 + b_r) * 144 + (kc + b_c) * 2);
                uint32_t t4[4];
                ldmx4(t4, sb + BHI + off);
                bh[2*np][0] = t4[0]; bh[2*np][1] = t4[1];
                bh[2*np+1][0] = t4[2]; bh[2*np+1][1] = t4[3];
                ldmx4(t4, sb + BLO + off);
                bl[2*np][0] = t4[0]; bl[2*np][1] = t4[1];
                bl[2*np+1][0] = t4[2]; bl[2*np+1][1] = t4[3];
            }
            #pragma unroll
            for (int mt = 0; mt < 2; mt++)
                #pragma unroll
                for (int nt = 0; nt < 4; nt++) {
                    mma16816(acc[mt][nt], ah[mt], bh[nt]);
                    mma16816(acc[mt][nt], ah[mt], bl[nt]);
                    mma16816(acc[mt][nt], al[mt], bh[nt]);
                }
        }
    }
    int g = lane >> 2, t = lane & 3;
    #pragma unroll
    for (int mt = 0; mt < 2; mt++) {
        long long r0 = row0 + warpM * 32 + mt * 16 + g;
        #pragma unroll
        for (int nt = 0; nt < 4; nt++) {
            int col = cbase + warpN * 32 + nt * 8 + t * 2;
            if (r0 < M)
                *reinterpret_cast<__half2*>(&g_h2[r0 * 2 * ODIM + col]) =
                    __floats2half2_rn(acc[mt][nt][0], acc[mt][nt][1]);
            if (r0 + 8 < M)
                *reinterpret_cast<__half2*>(&g_h2[(r0 + 8) * 2 * ODIM + col]) =
                    __floats2half2_rn(acc[mt][nt][2], acc[mt][nt][3]);
        }
    }
}

// ---------------- layer-1 aggregation: warp/node, both branches, fp32 out ----------------
__global__ void k_agg1(const float* __restrict__ b1, int n) {
    int node = (blockIdx.x * blockDim.x + threadIdx.x) >> 5;
    int lane = threadIdx.x & 31;
    if (node >= n) return;
    int s0 = g_colptr[node], s1 = g_colptr[node + 1];
    float4 ag = make_float4(0, 0, 0, 0);
    float4 ap = make_float4(0, 0, 0, 0);
    int e = s0;
    for (; e + 1 < s1; e += 2) {
        int sA = g_src[e], sB = g_src[e + 1];
        float gnA = g_gn[e], pnA = g_pn[e];
        float gnB = g_gn[e + 1], pnB = g_pn[e + 1];
        float4 vA = *reinterpret_cast<const float4*>(&g_h1[(size_t)sA * HDIM + lane * 4]);
        float4 vB = *reinterpret_cast<const float4*>(&g_h1[(size_t)sB * HDIM + lane * 4]);
        ag.x += gnA * vA.x + gnB * vB.x; ag.y += gnA * vA.y + gnB * vB.y;
        ag.z += gnA * vA.z + gnB * vB.z; ag.w += gnA * vA.w + gnB * vB.w;
        ap.x += pnA * vA.x + pnB * vB.x; ap.y += pnA * vA.y + pnB * vB.y;
        ap.z += pnA * vA.z + pnB * vB.z; ap.w += pnA * vA.w + pnB * vB.w;
    }
    if (e < s1) {
        int s = g_src[e];
        float gn = g_gn[e], pn = g_pn[e];
        float4 v = *reinterpret_cast<const float4*>(&g_h1[(size_t)s * HDIM + lane * 4]);
        ag.x += gn * v.x; ag.y += gn * v.y; ag.z += gn * v.z; ag.w += gn * v.w;
        ap.x += pn * v.x; ap.y += pn * v.y; ap.z += pn * v.z; ap.w += pn * v.w;
    }
    float dg = g_disg[node]; dg *= dg;
    float dp = g_disp[node]; dp *= dp;
    float4 v = *reinterpret_cast<const float4*>(&g_h1[(size_t)node * HDIM + lane * 4]);
    ag.x += dg * v.x; ag.y += dg * v.y; ag.z += dg * v.z; ag.w += dg * v.w;
    ap.x += dp * v.x; ap.y += dp * v.y; ap.z += dp * v.z; ap.w += dp * v.w;
    float4 bb = *reinterpret_cast<const float4*>(&b1[lane * 4]);
    ag.x = fmaxf(ag.x + bb.x, 0.f); ag.y = fmaxf(ag.y + bb.y, 0.f);
    ag.z = fmaxf(ag.z + bb.z, 0.f); ag.w = fmaxf(ag.w + bb.w, 0.f);
    ap.x = fmaxf(ap.x + bb.x, 0.f); ap.y = fmaxf(ap.y + bb.y, 0.f);
    ap.z = fmaxf(ap.z + bb.z, 0.f); ap.w = fmaxf(ap.w + bb.w, 0.f);
    size_t base = (size_t)node * HDIM + lane * 4;
    *reinterpret_cast<float4*>(&g_g1[base]) = ag;
    *reinterpret_cast<float4*>(&g_p1[base]) = ap;
}

// ---------------- layer-2 aggregation (fp16 gather) + attention combine ----------------
// lanes 0-15: GCN branch (h2 cols 0-63), lanes 16-31: PPMI branch (cols 64-127)
__device__ __forceinline__ void h2gather(size_t node, int lane, float4& a, float w) {
    uint2 u = *reinterpret_cast<const uint2*>(&g_h2[node * 2 * ODIM + lane * 4]);
    float2 f01 = __half22float2(*reinterpret_cast<__half2*>(&u.x));
    float2 f23 = __half22float2(*reinterpret_cast<__half2*>(&u.y));
    a.x += w * f01.x; a.y += w * f01.y; a.z += w * f23.x; a.w += w * f23.y;
}

__global__ void k_agg2_combine(const float* __restrict__ b2,
                               const float* __restrict__ dw,
                               const float* __restrict__ db,
                               float* __restrict__ out, int n) {
    int node = (blockIdx.x * blockDim.x + threadIdx.x) >> 5;
    int lane = threadIdx.x & 31;
    if (node >= n) return;
    int s0 = g_colptr[node], s1 = g_colptr[node + 1];
    const bool isg = lane < 16;
    float4 a = make_float4(0, 0, 0, 0);
    int e = s0;
    for (; e + 1 < s1; e += 2) {
        int sA = g_src[e], sB = g_src[e + 1];
        float wA = isg ? g_gn[e] : g_pn[e];
        float wB = isg ? g_gn[e + 1] : g_pn[e + 1];
        h2gather((size_t)sA, lane, a, wA);
        h2gather((size_t)sB, lane, a, wB);
    }
    if (e < s1) {
        int s = g_src[e];
        h2gather((size_t)s, lane, a, isg ? g_gn[e] : g_pn[e]);
    }
    float d = isg ? g_disg[node] : g_disp[node];
    d *= d;
    h2gather((size_t)node, lane, a, d);
    int c4 = (lane & 15) * 4;
    float4 bb = *reinterpret_cast<const float4*>(&b2[c4]);
    a.x += bb.x; a.y += bb.y; a.z += bb.z; a.w += bb.w;
    // per-branch logits via masked full-warp reduction
    float4 w4 = *reinterpret_cast<const float4*>(&dw[c4]);
    float dot = a.x * w4.x + a.y * w4.y + a.z * w4.z + a.w * w4.w;
    float pg = isg ? dot : 0.0f;
    float pp = isg ? 0.0f : dot;
    #pragma unroll
    for (int o = 16; o; o >>= 1) {
        pg += __shfl_xor_sync(0xffffffffu, pg, o);
        pp += __shfl_xor_sync(0xffffffffu, pp, o);
    }
    float bd = db[0];
    float lg = pg + bd, lp = pp + bd;
    float m = fmaxf(lg, lp);
    float eg = __expf(lg - m), ep = __expf(lp - m);
    float wg = eg / (eg + ep), wp = 1.0f - wg;
    float4 o4;
    o4.x = __shfl_xor_sync(0xffffffffu, a.x, 16);
    o4.y = __shfl_xor_sync(0xffffffffu, a.y, 16);
    o4.z = __shfl_xor_sync(0xffffffffu, a.z, 16);
    o4.w = __shfl_xor_sync(0xffffffffu, a.w, 16);
    if (isg) {
        float4 r;
        r.x = wg * a.x + wp * o4.x; r.y = wg * a.y + wp * o4.y;
        r.z = wg * a.z + wp * o4.z; r.w = wg * a.w + wp * o4.w;
        *reinterpret_cast<float4*>(&out[(size_t)node * ODIM + c4]) = r;
    }
}

// ---------------- launch ----------------
extern "C" void kernel_launch(void* const* d_in, const int* in_sizes, int n_in,
                              void* d_out, int out_size) {
    const float* x    = (const float*)d_in[0];
    const int*   ei   = (const int*)d_in[1];     // int32 [2, E]
    const float* ppmi = (const float*)d_in[2];
    const float* W1   = (const float*)d_in[3];
    const float* b1   = (const float*)d_in[4];
    const float* W2   = (const float*)d_in[5];
    const float* b2   = (const float*)d_in[6];
    const float* dw   = (const float*)d_in[7];
    const float* db   = (const float*)d_in[8];
    float*       out  = (float*)d_out;

    const int N = in_sizes[0] / DDIM;
    const int E = in_sizes[2];

    cudaFuncSetAttribute(k_gemm1_tc, cudaFuncAttributeMaxDynamicSharedMemorySize, G1_SMEM);
    cudaFuncSetAttribute(k_gemm2_tc, cudaFuncAttributeMaxDynamicSharedMemorySize, G2_SMEM);

    const int TB = 256;
    const bool fork = (g_s2 != nullptr) && (g_ev0 != nullptr) && (g_ev1 != nullptr);
    cudaStream_t sb = fork ? g_s2 : (cudaStream_t)0;

    // --- branch A (side stream): CSR graph build ---
    if (fork) {
        cudaEventRecord(g_ev0, 0);
        cudaStreamWaitEvent(g_s2, g_ev0, 0);
    }
    k_init<<<(N + TB - 1) / TB, TB, 0, sb>>>(N);
    k_deg<<<(E + TB - 1) / TB, TB, 0, sb>>>(ei, ppmi, E);
    k_rsqrt<<<(N + TB - 1) / TB, TB, 0, sb>>>(N);
    int nb = (N + 1023) / 1024;
    k_scan1<<<nb, 1024, 0, sb>>>(N);
    k_scan2<<<1, 128, 0, sb>>>(nb);
    k_scan3<<<nb, 1024, 0, sb>>>(N, E);
    k_fill<<<(E + TB - 1) / TB, TB, 0, sb>>>(ei, ppmi, E);
    if (fork) cudaEventRecord(g_ev1, g_s2);

    // --- branch B (capture stream): weight splits + GEMM1 ---
    k_splitW<<<(DDIM * HDIM + HDIM * ODIM + TB - 1) / TB, TB>>>(W1, W2);
    int g1 = (N + 127) / 128;
    k_gemm1_tc<<<g1, 256, G1_SMEM>>>(x, N);

    // --- join, then serial tail ---
    if (fork) cudaStreamWaitEvent((cudaStream_t)0, g_ev1, 0);
    k_agg1<<<(N * 32 + TB - 1) / TB, TB>>>(b1, N);
    dim3 grid2(g1, 2);
    k_gemm2_tc<<<grid2, 256, G2_SMEM>>>(N);
    k_agg2_combine<<<(N * 32 + TB - 1) / TB, TB>>>(b2, dw, db, out, N);
}

// round 14
// speedup vs baseline: 1.3481x; 1.0602x over previous
#include <cuda_runtime.h>
#include <cuda_bf16.h>
#include <cuda_fp16.h>
#include <cstdint>

// Problem-fixed dimensions (N=100000, E=1600000, D=256, H=128, O=64)
#define NMAX 100000
#define EMAX 1600000
#define DDIM 256
#define HDIM 128
#define ODIM 64

// ============================ warp-MMA helpers (plain sm_103 PTX) ============================
__device__ __forceinline__ uint32_t smem_to_u32(const void* p) {
    uint32_t a;
    asm("{ .reg .u64 t; cvta.to.shared.u64 t, %1; cvt.u32.u64 %0, t; }" : "=r"(a) : "l"(p));
    return a;
}
__device__ __forceinline__ void ldmx4(uint32_t* r, uint32_t addr) {
    asm volatile("ldmatrix.sync.aligned.m8n8.x4.shared.b16 {%0,%1,%2,%3}, [%4];"
        : "=r"(r[0]), "=r"(r[1]), "=r"(r[2]), "=r"(r[3]) : "r"(addr));
}
__device__ __forceinline__ void mma16816(float* d, const uint32_t* a, const uint32_t* b) {
    asm volatile("mma.sync.aligned.m16n8k16.row.col.f32.bf16.bf16.f32 "
        "{%0,%1,%2,%3}, {%4,%5,%6,%7}, {%8,%9}, {%0,%1,%2,%3};"
        : "+f"(d[0]), "+f"(d[1]), "+f"(d[2]), "+f"(d[3])
        : "r"(a[0]), "r"(a[1]), "r"(a[2]), "r"(a[3]), "r"(b[0]), "r"(b[1]));
}
__device__ __forceinline__ uint32_t bpack(__nv_bfloat16 a, __nv_bfloat16 b) {
    __nv_bfloat162 t = __halves2bfloat162(a, b);
    return *reinterpret_cast<uint32_t*>(&t);
}

// ---------------- device scratch (static, no allocation) ----------------
__device__ __half g_h1[NMAX*HDIM];                 // x @ W1 (fp16)
__device__ __half g_g1[NMAX*HDIM];                 // relu(agg_gcn(h1)+b1) fp16
__device__ __half g_p1[NMAX*HDIM];                 // relu(agg_ppmi(h1)+b1) fp16
__device__ __half g_h2[NMAX*2*ODIM];               // interleaved fp16: [node][0:64)=g, [64:128)=p
__device__ __nv_bfloat16 g_w1h[HDIM*DDIM];         // W1^T splits: [n=128][k=256]
__device__ __nv_bfloat16 g_w1l[HDIM*DDIM];
__device__ __nv_bfloat16 g_w2h[ODIM*HDIM];         // W2^T splits: [n=64][k=128]
__device__ __nv_bfloat16 g_w2l[ODIM*HDIM];
__device__ float g_disg[NMAX];
__device__ float g_disp[NMAX];
__device__ int   g_cnt   [NMAX];
__device__ int   g_cursor[NMAX];
__device__ int   g_colptr[NMAX+1];
__device__ int   g_src[EMAX];
__device__ float g_gn [EMAX];
__device__ float g_pn [EMAX];
__device__ int   g_bsums[128];

// ---------------- static stream/event fork (created at load; falls back to serial) ----------
static cudaStream_t g_s2 = nullptr;
static cudaEvent_t  g_ev0 = nullptr, g_ev1 = nullptr;
namespace {
struct ForkInit {
    ForkInit() {
        if (cudaStreamCreateWithFlags(&g_s2, cudaStreamNonBlocking) != cudaSuccess) g_s2 = nullptr;
        if (cudaEventCreateWithFlags(&g_ev0, cudaEventDisableTiming) != cudaSuccess) g_ev0 = nullptr;
        if (cudaEventCreateWithFlags(&g_ev1, cudaEventDisableTiming) != cudaSuccess) g_ev1 = nullptr;
    }
};
ForkInit g_forkinit;
}

// ---------------- graph build (re-run every replay) ----------------
__global__ void k_init(int n) {
    int i = blockIdx.x * blockDim.x + threadIdx.x;
    if (i < n) { g_cnt[i] = 0; g_cursor[i] = 0; g_disg[i] = 1.0f; g_disp[i] = 1.0f; }
}

__global__ void k_deg(const int* __restrict__ ei, const float* __restrict__ ppmi, int E) {
    int e = blockIdx.x * blockDim.x + threadIdx.x;
    if (e < E) {
        int r = ei[e]; int c = ei[E + e];
        atomicAdd(&g_disg[r], 1.0f);
        atomicAdd(&g_disp[r], ppmi[e]);
        atomicAdd(&g_cnt[c], 1);
    }
}

__global__ void k_rsqrt(int n) {
    int i = blockIdx.x * blockDim.x + threadIdx.x;
    if (i < n) { g_disg[i] = rsqrtf(g_disg[i]); g_disp[i] = rsqrtf(g_disp[i]); }
}

__global__ void k_scan1(int n) {
    __shared__ int wsum[32];
    int i = blockIdx.x * 1024 + threadIdx.x;
    int v = (i < n) ? g_cnt[i] : 0;
    int x = v;
    #pragma unroll
    for (int o = 1; o < 32; o <<= 1) {
        int y = __shfl_up_sync(0xffffffffu, x, o);
        if ((threadIdx.x & 31) >= o) x += y;
    }
    if ((threadIdx.x & 31) == 31) wsum[threadIdx.x >> 5] = x;
    __syncthreads();
    if (threadIdx.x < 32) {
        int s = wsum[threadIdx.x];
        #pragma unroll
        for (int o = 1; o < 32; o <<= 1) {
            int y = __shfl_up_sync(0xffffffffu, s, o);
            if (threadIdx.x >= o) s += y;
        }
        wsum[threadIdx.x] = s;
    }
    __syncthreads();
    int base = (threadIdx.x >= 32) ? wsum[(threadIdx.x >> 5) - 1] : 0;
    int incl = base + x;
    if (i < n) g_colptr[i] = incl - v;
    if (threadIdx.x == 1023) g_bsums[blockIdx.x] = incl;
}

__global__ void k_scan2(int nb) {
    __shared__ int s[128];
    int t = threadIdx.x;
    s[t] = (t < nb) ? g_bsums[t] : 0;
    __syncthreads();
    for (int o = 1; o < 128; o <<= 1) {
        int y = (t >= o) ? s[t - o] : 0;
        __syncthreads();
        s[t] += y;
        __syncthreads();
    }
    if (t < nb) g_bsums[t] = (t > 0) ? s[t - 1] : 0;
}

__global__ void k_scan3(int n, int E) {
    int i = blockIdx.x * 1024 + threadIdx.x;
    if (i < n) g_colptr[i] += g_bsums[blockIdx.x];
    if (i == 0) g_colptr[n] = E;
}

__global__ void k_fill(const int* __restrict__ ei, const float* __restrict__ ppmi, int E) {
    int e = blockIdx.x * blockDim.x + threadIdx.x;
    if (e >= E) return;
    int r = ei[e]; int c = ei[E + e];
    int pos = g_colptr[c] + atomicAdd(&g_cursor[c], 1);
    g_src[pos] = r;
    g_gn[pos] = g_disg[r] * g_disg[c];
    g_pn[pos] = g_disp[r] * ppmi[e] * g_disp[c];
}

// ---------------- weight split prep: both W1 and W2 in one launch ----------------
__global__ void k_splitW(const float* __restrict__ W1, const float* __restrict__ W2) {
    int i = blockIdx.x * blockDim.x + threadIdx.x;
    if (i < DDIM * HDIM) {                       // W1 [256,128] -> T splits [128][256]
        int k = i >> 7, nn = i & 127;
        float v = W1[k * HDIM + nn];
        __nv_bfloat16 h = __float2bfloat16(v);
        g_w1h[nn * DDIM + k] = h;
        g_w1l[nn * DDIM + k] = __float2bfloat16(v - __bfloat162float(h));
    } else if (i < DDIM * HDIM + HDIM * ODIM) {  // W2 [128,64] -> T splits [64][128]
        int j = i - DDIM * HDIM;
        int k = j >> 6, nn = j & 63;
        float v = W2[k * ODIM + nn];
        __nv_bfloat16 h = __float2bfloat16(v);
        g_w2h[nn * HDIM + k] = h;
        g_w2l[nn * HDIM + k] = __float2bfloat16(v - __bfloat162float(h));
    }
}

// ---------------- SMEM tile fill: ROWS x 64 bf16, padded row stride 144 B ----------------
template <int ROWS>
__device__ __forceinline__ void fill_pad(char* smem, int dst_off,
                                         const uint4* __restrict__ src,  // 8 bf16 per uint4
                                         long long first_row, int stride_u4, int k0_u4,
                                         int nvalid, int tid) {
    for (int u = tid; u < ROWS * 8; u += 256) {
        int r = u >> 3, c = u & 7;
        uint4 v = make_uint4(0, 0, 0, 0);
        if (r < nvalid) v = src[(size_t)(first_row + r) * stride_u4 + k0_u4 + c];
        *reinterpret_cast<uint4*>(smem + dst_off + r * 144 + c * 16) = v;
    }
}

// fp32 source -> hi/lo bf16 tiles in one pass (ROWS x 64 cols)
template <int ROWS>
__device__ __forceinline__ void fill_split(char* smem, int hi_off, int lo_off,
                                           const float4* __restrict__ src,  // 4 fp32 per float4
                                           long long first_row, int stride_f4, int k0_f4,
                                           int nvalid, int tid) {
    for (int u = tid; u < ROWS * 16; u += 256) {
        int r = u >> 4, c = u & 15;
        float4 v = make_float4(0, 0, 0, 0);
        if (r < nvalid) v = src[(size_t)(first_row + r) * stride_f4 + k0_f4 + c];
        __nv_bfloat16 hx = __float2bfloat16(v.x), hy = __float2bfloat16(v.y);
        __nv_bfloat16 hz = __float2bfloat16(v.z), hw = __float2bfloat16(v.w);
        uint2 hi2 = make_uint2(bpack(hx, hy), bpack(hz, hw));
        uint2 lo2 = make_uint2(
            bpack(__float2bfloat16(v.x - __bfloat162float(hx)), __float2bfloat16(v.y - __bfloat162float(hy))),
            bpack(__float2bfloat16(v.z - __bfloat162float(hz)), __float2bfloat16(v.w - __bfloat162float(hw))));
        int bo = r * 144 + c * 8;
        *reinterpret_cast<uint2*>(smem + hi_off + bo) = hi2;
        *reinterpret_cast<uint2*>(smem + lo_off + bo) = lo2;
    }
}

// fp16 source -> hi/lo bf16 tiles (fp16 = bf16hi + bf16lo exactly); ROWS x 64 cols
template <int ROWS>
__device__ __forceinline__ void fill_split_h(char* smem, int hi_off, int lo_off,
                                             const uint4* __restrict__ src,  // 8 fp16 per uint4
                                             long long first_row, int stride_u4, int k0_u4,
                                             int nvalid, int tid) {
    for (int u = tid; u < ROWS * 8; u += 256) {
        int r = u >> 3, c = u & 7;
        uint4 v = make_uint4(0, 0, 0, 0);
        if (r < nvalid) v = src[(size_t)(first_row + r) * stride_u4 + k0_u4 + c];
        const __half2* hp = reinterpret_cast<const __half2*>(&v);
        uint32_t hi[4], lo[4];
        #pragma unroll
        for (int j = 0; j < 4; j++) {
            float2 f = __half22float2(hp[j]);
            __nv_bfloat16 ha = __float2bfloat16(f.x), hb = __float2bfloat16(f.y);
            hi[j] = bpack(ha, hb);
            lo[j] = bpack(__float2bfloat16(f.x - __bfloat162float(ha)),
                          __float2bfloat16(f.y - __bfloat162float(hb)));
        }
        int bo = r * 144 + c * 16;
        *reinterpret_cast<uint4*>(smem + hi_off + bo) = make_uint4(hi[0], hi[1], hi[2], hi[3]);
        *reinterpret_cast<uint4*>(smem + lo_off + bo) = make_uint4(lo[0], lo[1], lo[2], lo[3]);
    }
}

// ---------------- GEMM1: h1[M,128] (fp16) = x[M,256] @ W1 via bf16x3 mma.sync ----------------
static constexpr int G1_SMEM = 4 * 18432;   // Ahi/Alo/Bhi/Blo, 128 rows x 144B
__global__ void __launch_bounds__(256) k_gemm1_tc(const float* __restrict__ x, int M) {
    extern __shared__ char smem[];
    uint32_t sb = smem_to_u32(smem);
    const int tid = threadIdx.x, wid = tid >> 5, lane = tid & 31;
    const int warpM = wid & 3, warpN = wid >> 2;          // 4 x 2 warps
    const int AHI = 0, ALO = 18432, BHI = 36864, BLO = 55296;

    long long row0 = (long long)blockIdx.x * 128;
    int nvalid = (int)((M - row0 < 128) ? (M - row0) : 128);
    const float4* x4 = reinterpret_cast<const float4*>(x);
    const uint4* wh = reinterpret_cast<const uint4*>(g_w1h);
    const uint4* wl = reinterpret_cast<const uint4*>(g_w1l);

    float acc[2][8][4];
    #pragma unroll
    for (int i = 0; i < 2; i++)
        #pragma unroll
        for (int j = 0; j < 8; j++)
            #pragma unroll
            for (int k = 0; k < 4; k++) acc[i][j][k] = 0.0f;

    const int a_r = (lane & 7) + ((lane & 8) ? 8 : 0);
    const int a_c = (lane & 16) ? 8 : 0;
    const int b_r = (lane & 7) + ((lane & 16) ? 8 : 0);
    const int b_c = (lane & 8) ? 8 : 0;

    #pragma unroll 1
    for (int c = 0; c < 4; c++) {                         // K chunks of 64 (K=256)
        if (c) __syncthreads();
        fill_split<128>(smem, AHI, ALO, x4, row0, 64, c * 16, nvalid, tid);
        fill_pad<128>(smem, BHI, wh, 0, 32, c * 8, 128, tid);
        fill_pad<128>(smem, BLO, wl, 0, 32, c * 8, 128, tid);
        __syncthreads();
        #pragma unroll
        for (int k16 = 0; k16 < 4; k16++) {
            int kc = k16 * 16;
            uint32_t ah[2][4], al[2][4];
            #pragma unroll
            for (int mt = 0; mt < 2; mt++) {
                uint32_t off = (uint32_t)((warpM * 32 + mt * 16 + a_r) * 144 + (kc + a_c) * 2);
                ldmx4(ah[mt], sb + AHI + off);
                ldmx4(al[mt], sb + ALO + off);
            }
            uint32_t bh[8][2], bl[8][2];
            #pragma unroll
            for (int np = 0; np < 4; np++) {
                uint32_t off = (uint32_t)((warpN * 64 + np * 16 + b_r) * 144 + (kc + b_c) * 2);
                uint32_t t4[4];
                ldmx4(t4, sb + BHI + off);
                bh[2*np][0] = t4[0]; bh[2*np][1] = t4[1];
                bh[2*np+1][0] = t4[2]; bh[2*np+1][1] = t4[3];
                ldmx4(t4, sb + BLO + off);
                bl[2*np][0] = t4[0]; bl[2*np][1] = t4[1];
                bl[2*np+1][0] = t4[2]; bl[2*np+1][1] = t4[3];
            }
            #pragma unroll
            for (int mt = 0; mt < 2; mt++)
                #pragma unroll
                for (int nt = 0; nt < 8; nt++) {
                    mma16816(acc[mt][nt], ah[mt], bh[nt]);
                    mma16816(acc[mt][nt], ah[mt], bl[nt]);
                    mma16816(acc[mt][nt], al[mt], bh[nt]);
                }
        }
    }
    int g = lane >> 2, t = lane & 3;
    #pragma unroll
    for (int mt = 0; mt < 2; mt++) {
        long long r0 = row0 + warpM * 32 + mt * 16 + g;
        #pragma unroll
        for (int nt = 0; nt < 8; nt++) {
            int col = warpN * 64 + nt * 8 + t * 2;
            if (r0 < M)
                *reinterpret_cast<__half2*>(&g_h1[r0 * HDIM + col]) =
                    __floats2half2_rn(acc[mt][nt][0], acc[mt][nt][1]);
            if (r0 + 8 < M)
                *reinterpret_cast<__half2*>(&g_h1[(r0 + 8) * HDIM + col]) =
                    __floats2half2_rn(acc[mt][nt][2], acc[mt][nt][3]);
        }
    }
}

// ---------------- GEMM2: h2 fp16 interleaved = {g1,p1}(fp16) @ W2 via bf16x3 mma.sync --------
static constexpr int G2_SMEM = 2 * 18432 + 2 * 9216;
__global__ void __launch_bounds__(256) k_gemm2_tc(int M) {
    extern __shared__ char smem[];
    uint32_t sb = smem_to_u32(smem);
    const int tid = threadIdx.x, wid = tid >> 5, lane = tid & 31;
    const int warpM = wid & 3, warpN = wid >> 2;          // 4 x 2 warps, warp tile 32x32
    const int AHI = 0, ALO = 18432, BHI = 36864, BLO = 46080;

    long long row0 = (long long)blockIdx.x * 128;
    int nvalid = (int)((M - row0 < 128) ? (M - row0) : 128);
    const uint4* a4 = reinterpret_cast<const uint4*>(blockIdx.y ? g_p1 : g_g1);  // 8 fp16/uint4
    const uint4* wh = reinterpret_cast<const uint4*>(g_w2h);
    const uint4* wl = reinterpret_cast<const uint4*>(g_w2l);
    const int cbase = blockIdx.y * ODIM;

    float acc[2][4][4];
    #pragma unroll
    for (int i = 0; i < 2; i++)
        #pragma unroll
        for (int j = 0; j < 4; j++)
            #pragma unroll
            for (int k = 0; k < 4; k++) acc[i][j][k] = 0.0f;

    const int a_r = (lane & 7) + ((lane & 8) ? 8 : 0);
    const int a_c = (lane & 16) ? 8 : 0;
    const int b_r = (lane & 7) + ((lane & 16) ? 8 : 0);
    const int b_c = (lane & 8) ? 8 : 0;

    #pragma unroll 1
    for (int c = 0; c < 2; c++) {                         // K chunks of 64 (K=128)
        if (c) __syncthreads();
        fill_split_h<128>(smem, AHI, ALO, a4, row0, 16, c * 8, nvalid, tid);
        fill_pad<64>(smem, BHI, wh, 0, 16, c * 8, 64, tid);
        fill_pad<64>(smem, BLO, wl, 0, 16, c * 8, 64, tid);
        __syncthreads();
        #pragma unroll
        for (int k16 = 0; k16 < 4; k16++) {
            int kc = k16 * 16;
            uint32_t ah[2][4], al[2][4];
            #pragma unroll
            for (int mt = 0; mt < 2; mt++) {
                uint32_t off = (uint32_t)((warpM * 32 + mt * 16 + a_r) * 144 + (kc + a_c) * 2);
                ldmx4(ah[mt], sb + AHI + off);
                ldmx4(al[mt], sb + ALO + off);
            }
            uint32_t bh[4][2], bl[4][2];
            #pragma unroll
            for (int np = 0; np < 2; np++) {
                uint32_t off = (uint32_t)((warpN * 32 + np * 16 + b_r) * 144 + (kc + b_c) * 2);
                uint32_t t4[4];
                ldmx4(t4, sb + BHI + off);
                bh[2*np][0] = t4[0]; bh[2*np][1] = t4[1];
                bh[2*np+1][0] = t4[2]; bh[2*np+1][1] = t4[3];
                ldmx4(t4, sb + BLO + off);
                bl[2*np][0] = t4[0]; bl[2*np][1] = t4[1];
                bl[2*np+1][0] = t4[2]; bl[2*np+1][1] = t4[3];
            }
            #pragma unroll
            for (int mt = 0; mt < 2; mt++)
                #pragma unroll
                for (int nt = 0; nt < 4; nt++) {
                    mma16816(acc[mt][nt], ah[mt], bh[nt]);
                    mma16816(acc[mt][nt], ah[mt], bl[nt]);
                    mma16816(acc[mt][nt], al[mt], bh[nt]);
                }
        }
    }
    int g = lane >> 2, t = lane & 3;
    #pragma unroll
    for (int mt = 0; mt < 2; mt++) {
        long long r0 = row0 + warpM * 32 + mt * 16 + g;
        #pragma unroll
        for (int nt = 0; nt < 4; nt++) {
            int col = cbase + warpN * 32 + nt * 8 + t * 2;
            if (r0 < M)
                *reinterpret_cast<__half2*>(&g_h2[r0 * 2 * ODIM + col]) =
                    __floats2half2_rn(acc[mt][nt][0], acc[mt][nt][1]);
            if (r0 + 8 < M)
                *reinterpret_cast<__half2*>(&g_h2[(r0 + 8) * 2 * ODIM + col]) =
                    __floats2half2_rn(acc[mt][nt][2], acc[mt][nt][3]);
        }
    }
}

// ---------------- layer-1 aggregation: warp/node, fp16 gather, fp16 out ----------------
__device__ __forceinline__ float4 h1load(size_t node, int lane) {
    uint2 u = *reinterpret_cast<const uint2*>(&g_h1[node * HDIM + lane * 4]);
    float2 f01 = __half22float2(*reinterpret_cast<__half2*>(&u.x));
    float2 f23 = __half22float2(*reinterpret_cast<__half2*>(&u.y));
    return make_float4(f01.x, f01.y, f23.x, f23.y);
}

__global__ void k_agg1(const float* __restrict__ b1, int n) {
    int node = (blockIdx.x * blockDim.x + threadIdx.x) >> 5;
    int lane = threadIdx.x & 31;
    if (node >= n) return;
    int s0 = g_colptr[node], s1 = g_colptr[node + 1];
    float4 ag = make_float4(0, 0, 0, 0);
    float4 ap = make_float4(0, 0, 0, 0);
    int e = s0;
    for (; e + 1 < s1; e += 2) {
        int sA = g_src[e], sB = g_src[e + 1];
        float gnA = g_gn[e], pnA = g_pn[e];
        float gnB = g_gn[e + 1], pnB = g_pn[e + 1];
        float4 vA = h1load((size_t)sA, lane);
        float4 vB = h1load((size_t)sB, lane);
        ag.x += gnA * vA.x + gnB * vB.x; ag.y += gnA * vA.y + gnB * vB.y;
        ag.z += gnA * vA.z + gnB * vB.z; ag.w += gnA * vA.w + gnB * vB.w;
        ap.x += pnA * vA.x + pnB * vB.x; ap.y += pnA * vA.y + pnB * vB.y;
        ap.z += pnA * vA.z + pnB * vB.z; ap.w += pnA * vA.w + pnB * vB.w;
    }
    if (e < s1) {
        int s = g_src[e];
        float gn = g_gn[e], pn = g_pn[e];
        float4 v = h1load((size_t)s, lane);
        ag.x += gn * v.x; ag.y += gn * v.y; ag.z += gn * v.z; ag.w += gn * v.w;
        ap.x += pn * v.x; ap.y += pn * v.y; ap.z += pn * v.z; ap.w += pn * v.w;
    }
    float dg = g_disg[node]; dg *= dg;
    float dp = g_disp[node]; dp *= dp;
    float4 v = h1load((size_t)node, lane);
    ag.x += dg * v.x; ag.y += dg * v.y; ag.z += dg * v.z; ag.w += dg * v.w;
    ap.x += dp * v.x; ap.y += dp * v.y; ap.z += dp * v.z; ap.w += dp * v.w;
    float4 bb = *reinterpret_cast<const float4*>(&b1[lane * 4]);
    ag.x = fmaxf(ag.x + bb.x, 0.f); ag.y = fmaxf(ag.y + bb.y, 0.f);
    ag.z = fmaxf(ag.z + bb.z, 0.f); ag.w = fmaxf(ag.w + bb.w, 0.f);
    ap.x = fmaxf(ap.x + bb.x, 0.f); ap.y = fmaxf(ap.y + bb.y, 0.f);
    ap.z = fmaxf(ap.z + bb.z, 0.f); ap.w = fmaxf(ap.w + bb.w, 0.f);
    size_t base = (size_t)node * HDIM + lane * 4;
    __half2* gdst = reinterpret_cast<__half2*>(&g_g1[base]);
    gdst[0] = __floats2half2_rn(ag.x, ag.y);
    gdst[1] = __floats2half2_rn(ag.z, ag.w);
    __half2* pdst = reinterpret_cast<__half2*>(&g_p1[base]);
    pdst[0] = __floats2half2_rn(ap.x, ap.y);
    pdst[1] = __floats2half2_rn(ap.z, ap.w);
}

// ---------------- layer-2 aggregation (fp16 gather) + attention combine ----------------
// lanes 0-15: GCN branch (h2 cols 0-63), lanes 16-31: PPMI branch (cols 64-127)
__device__ __forceinline__ void h2gather(size_t node, int lane, float4& a, float w) {
    uint2 u = *reinterpret_cast<const uint2*>(&g_h2[node * 2 * ODIM + lane * 4]);
    float2 f01 = __half22float2(*reinterpret_cast<__half2*>(&u.x));
    float2 f23 = __half22float2(*reinterpret_cast<__half2*>(&u.y));
    a.x += w * f01.x; a.y += w * f01.y; a.z += w * f23.x; a.w += w * f23.y;
}

__global__ void k_agg2_combine(const float* __restrict__ b2,
                               const float* __restrict__ dw,
                               const float* __restrict__ db,
                               float* __restrict__ out, int n) {
    int node = (blockIdx.x * blockDim.x + threadIdx.x) >> 5;
    int lane = threadIdx.x & 31;
    if (node >= n) return;
    int s0 = g_colptr[node], s1 = g_colptr[node + 1];
    const bool isg = lane < 16;
    float4 a = make_float4(0, 0, 0, 0);
    int e = s0;
    for (; e + 1 < s1; e += 2) {
        int sA = g_src[e], sB = g_src[e + 1];
        float wA = isg ? g_gn[e] : g_pn[e];
        float wB = isg ? g_gn[e + 1] : g_pn[e + 1];
        h2gather((size_t)sA, lane, a, wA);
        h2gather((size_t)sB, lane, a, wB);
    }
    if (e < s1) {
        int s = g_src[e];
        h2gather((size_t)s, lane, a, isg ? g_gn[e] : g_pn[e]);
    }
    float d = isg ? g_disg[node] : g_disp[node];
    d *= d;
    h2gather((size_t)node, lane, a, d);
    int c4 = (lane & 15) * 4;
    float4 bb = *reinterpret_cast<const float4*>(&b2[c4]);
    a.x += bb.x; a.y += bb.y; a.z += bb.z; a.w += bb.w;
    // per-branch logits via masked full-warp reduction
    float4 w4 = *reinterpret_cast<const float4*>(&dw[c4]);
    float dot = a.x * w4.x + a.y * w4.y + a.z * w4.z + a.w * w4.w;
    float pg = isg ? dot : 0.0f;
    float pp = isg ? 0.0f : dot;
    #pragma unroll
    for (int o = 16; o; o >>= 1) {
        pg += __shfl_xor_sync(0xffffffffu, pg, o);
        pp += __shfl_xor_sync(0xffffffffu, pp, o);
    }
    float bd = db[0];
    float lg = pg + bd, lp = pp + bd;
    float m = fmaxf(lg, lp);
    float eg = __expf(lg - m), ep = __expf(lp - m);
    float wg = eg / (eg + ep), wp = 1.0f - wg;
    float4 o4;
    o4.x = __shfl_xor_sync(0xffffffffu, a.x, 16);
    o4.y = __shfl_xor_sync(0xffffffffu, a.y, 16);
    o4.z = __shfl_xor_sync(0xffffffffu, a.z, 16);
    o4.w = __shfl_xor_sync(0xffffffffu, a.w, 16);
    if (isg) {
        float4 r;
        r.x = wg * a.x + wp * o4.x; r.y = wg * a.y + wp * o4.y;
        r.z = wg * a.z + wp * o4.z; r.w = wg * a.w + wp * o4.w;
        *reinterpret_cast<float4*>(&out[(size_t)node * ODIM + c4]) = r;
    }
}

// ---------------- launch ----------------
extern "C" void kernel_launch(void* const* d_in, const int* in_sizes, int n_in,
                              void* d_out, int out_size) {
    const float* x    = (const float*)d_in[0];
    const int*   ei   = (const int*)d_in[1];     // int32 [2, E]
    const float* ppmi = (const float*)d_in[2];
    const float* W1   = (const float*)d_in[3];
    const float* b1   = (const float*)d_in[4];
    const float* W2   = (const float*)d_in[5];
    const float* b2   = (const float*)d_in[6];
    const float* dw   = (const float*)d_in[7];
    const float* db   = (const float*)d_in[8];
    float*       out  = (float*)d_out;

    const int N = in_sizes[0] / DDIM;
    const int E = in_sizes[2];

    cudaFuncSetAttribute(k_gemm1_tc, cudaFuncAttributeMaxDynamicSharedMemorySize, G1_SMEM);
    cudaFuncSetAttribute(k_gemm2_tc, cudaFuncAttributeMaxDynamicSharedMemorySize, G2_SMEM);

    const int TB = 256;
    const bool fork = (g_s2 != nullptr) && (g_ev0 != nullptr) && (g_ev1 != nullptr);
    cudaStream_t sb = fork ? g_s2 : (cudaStream_t)0;

    // --- branch A (side stream): CSR graph build ---
    if (fork) {
        cudaEventRecord(g_ev0, 0);
        cudaStreamWaitEvent(g_s2, g_ev0, 0);
    }
    k_init<<<(N + TB - 1) / TB, TB, 0, sb>>>(N);
    k_deg<<<(E + TB - 1) / TB, TB, 0, sb>>>(ei, ppmi, E);
    k_rsqrt<<<(N + TB - 1) / TB, TB, 0, sb>>>(N);
    int nb = (N + 1023) / 1024;
    k_scan1<<<nb, 1024, 0, sb>>>(N);
    k_scan2<<<1, 128, 0, sb>>>(nb);
    k_scan3<<<nb, 1024, 0, sb>>>(N, E);
    k_fill<<<(E + TB - 1) / TB, TB, 0, sb>>>(ei, ppmi, E);
    if (fork) cudaEventRecord(g_ev1, g_s2);

    // --- branch B (capture stream): weight splits + GEMM1 ---
    k_splitW<<<(DDIM * HDIM + HDIM * ODIM + TB - 1) / TB, TB>>>(W1, W2);
    int g1 = (N + 127) / 128;
    k_gemm1_tc<<<g1, 256, G1_SMEM>>>(x, N);

    // --- join, then serial tail ---
    if (fork) cudaStreamWaitEvent((cudaStream_t)0, g_ev1, 0);
    k_agg1<<<(N * 32 + TB - 1) / TB, TB>>>(b1, N);
    dim3 grid2(g1, 2);
    k_gemm2_tc<<<grid2, 256, G2_SMEM>>>(N);
    k_agg2_combine<<<(N * 32 + TB - 1) / TB, TB>>>(b2, dw, db, out, N);
}

// round 15
// speedup vs baseline: 1.6988x; 1.2601x over previous
#include <cuda_runtime.h>
#include <cuda_bf16.h>
#include <cuda_fp16.h>
#include <cstdint>

// Problem-fixed dimensions (N=100000, E=1600000, D=256, H=128, O=64)
#define NMAX 100000
#define EMAX 1600000
#define DDIM 256
#define HDIM 128
#define ODIM 64

// ============================ warp-MMA helpers (plain sm_103 PTX) ============================
__device__ __forceinline__ uint32_t smem_to_u32(const void* p) {
    uint32_t a;
    asm("{ .reg .u64 t; cvta.to.shared.u64 t, %1; cvt.u32.u64 %0, t; }" : "=r"(a) : "l"(p));
    return a;
}
__device__ __forceinline__ void ldmx4(uint32_t* r, uint32_t addr) {
    asm volatile("ldmatrix.sync.aligned.m8n8.x4.shared.b16 {%0,%1,%2,%3}, [%4];"
        : "=r"(r[0]), "=r"(r[1]), "=r"(r[2]), "=r"(r[3]) : "r"(addr));
}
// fp16 x fp16 -> fp32 accumulate (products exact: 11x11 bits < 24)
__device__ __forceinline__ void mma16816h(float* d, const uint32_t* a, const uint32_t* b) {
    asm volatile("mma.sync.aligned.m16n8k16.row.col.f32.f16.f16.f32 "
        "{%0,%1,%2,%3}, {%4,%5,%6,%7}, {%8,%9}, {%0,%1,%2,%3};"
        : "+f"(d[0]), "+f"(d[1]), "+f"(d[2]), "+f"(d[3])
        : "r"(a[0]), "r"(a[1]), "r"(a[2]), "r"(a[3]), "r"(b[0]), "r"(b[1]));
}
__device__ __forceinline__ uint32_t hpack(__half a, __half b) {
    __half2 t = __halves2half2(a, b);
    return *reinterpret_cast<uint32_t*>(&t);
}

// ---------------- device scratch (static, no allocation) ----------------
__device__ __half g_h1[NMAX*HDIM];                 // x @ W1 (fp16)
__device__ __half g_g1[NMAX*HDIM];                 // relu(agg_gcn(h1)+b1) fp16
__device__ __half g_p1[NMAX*HDIM];                 // relu(agg_ppmi(h1)+b1) fp16
__device__ __half g_h2[NMAX*2*ODIM];               // interleaved fp16: [node][0:64)=g, [64:128)=p
__device__ __half g_w1[HDIM*DDIM];                 // W1^T fp16: [n=128][k=256]
__device__ __half g_w2[ODIM*HDIM];                 // W2^T fp16: [n=64][k=128]
__device__ float g_disg[NMAX];
__device__ float g_disp[NMAX];
__device__ int   g_cnt   [NMAX];
__device__ int   g_cursor[NMAX];
__device__ int   g_colptr[NMAX+1];
__device__ int   g_src[EMAX];
__device__ float g_gn [EMAX];
__device__ float g_pn [EMAX];
__device__ int   g_bsums[128];

// ---------------- static stream/event fork (created at load; falls back to serial) ----------
static cudaStream_t g_s2 = nullptr;
static cudaEvent_t  g_ev0 = nullptr, g_ev1 = nullptr;
namespace {
struct ForkInit {
    ForkInit() {
        if (cudaStreamCreateWithFlags(&g_s2, cudaStreamNonBlocking) != cudaSuccess) g_s2 = nullptr;
        if (cudaEventCreateWithFlags(&g_ev0, cudaEventDisableTiming) != cudaSuccess) g_ev0 = nullptr;
        if (cudaEventCreateWithFlags(&g_ev1, cudaEventDisableTiming) != cudaSuccess) g_ev1 = nullptr;
    }
};
ForkInit g_forkinit;
}

// ---------------- graph build (re-run every replay) ----------------
__global__ void k_init(int n) {
    int i = blockIdx.x * blockDim.x + threadIdx.x;
    if (i < n) { g_cnt[i] = 0; g_cursor[i] = 0; g_disg[i] = 1.0f; g_disp[i] = 1.0f; }
}

__global__ void k_deg(const int* __restrict__ ei, const float* __restrict__ ppmi, int E) {
    int e = blockIdx.x * blockDim.x + threadIdx.x;
    if (e < E) {
        int r = ei[e]; int c = ei[E + e];
        atomicAdd(&g_disg[r], 1.0f);
        atomicAdd(&g_disp[r], ppmi[e]);
        atomicAdd(&g_cnt[c], 1);
    }
}

__global__ void k_rsqrt(int n) {
    int i = blockIdx.x * blockDim.x + threadIdx.x;
    if (i < n) { g_disg[i] = rsqrtf(g_disg[i]); g_disp[i] = rsqrtf(g_disp[i]); }
}

__global__ void k_scan1(int n) {
    __shared__ int wsum[32];
    int i = blockIdx.x * 1024 + threadIdx.x;
    int v = (i < n) ? g_cnt[i] : 0;
    int x = v;
    #pragma unroll
    for (int o = 1; o < 32; o <<= 1) {
        int y = __shfl_up_sync(0xffffffffu, x, o);
        if ((threadIdx.x & 31) >= o) x += y;
    }
    if ((threadIdx.x & 31) == 31) wsum[threadIdx.x >> 5] = x;
    __syncthreads();
    if (threadIdx.x < 32) {
        int s = wsum[threadIdx.x];
        #pragma unroll
        for (int o = 1; o < 32; o <<= 1) {
            int y = __shfl_up_sync(0xffffffffu, s, o);
            if (threadIdx.x >= o) s += y;
        }
        wsum[threadIdx.x] = s;
    }
    __syncthreads();
    int base = (threadIdx.x >= 32) ? wsum[(threadIdx.x >> 5) - 1] : 0;
    int incl = base + x;
    if (i < n) g_colptr[i] = incl - v;
    if (threadIdx.x == 1023) g_bsums[blockIdx.x] = incl;
}

__global__ void k_scan2(int nb) {
    __shared__ int s[128];
    int t = threadIdx.x;
    s[t] = (t < nb) ? g_bsums[t] : 0;
    __syncthreads();
    for (int o = 1; o < 128; o <<= 1) {
        int y = (t >= o) ? s[t - o] : 0;
        __syncthreads();
        s[t] += y;
        __syncthreads();
    }
    if (t < nb) g_bsums[t] = (t > 0) ? s[t - 1] : 0;
}

__global__ void k_scan3(int n, int E) {
    int i = blockIdx.x * 1024 + threadIdx.x;
    if (i < n) g_colptr[i] += g_bsums[blockIdx.x];
    if (i == 0) g_colptr[n] = E;
}

__global__ void k_fill(const int* __restrict__ ei, const float* __restrict__ ppmi, int E) {
    int e = blockIdx.x * blockDim.x + threadIdx.x;
    if (e >= E) return;
    int r = ei[e]; int c = ei[E + e];
    int pos = g_colptr[c] + atomicAdd(&g_cursor[c], 1);
    g_src[pos] = r;
    g_gn[pos] = g_disg[r] * g_disg[c];
    g_pn[pos] = g_disp[r] * ppmi[e] * g_disp[c];
}

// ---------------- weight prep: transpose to [n][k] fp16, one launch ----------------
__global__ void k_splitW(const float* __restrict__ W1, const float* __restrict__ W2) {
    int i = blockIdx.x * blockDim.x + threadIdx.x;
    if (i < DDIM * HDIM) {                       // W1 [256,128] -> T fp16 [128][256]
        int k = i >> 7, nn = i & 127;
        g_w1[nn * DDIM + k] = __float2half(W1[k * HDIM + nn]);
    } else if (i < DDIM * HDIM + HDIM * ODIM) {  // W2 [128,64] -> T fp16 [64][128]
        int j = i - DDIM * HDIM;
        int k = j >> 6, nn = j & 63;
        g_w2[nn * HDIM + k] = __float2half(W2[k * ODIM + nn]);
    }
}

// ---------------- SMEM tile fill: ROWS x 64 halfwords, padded row stride 144 B ----------------
template <int ROWS>
__device__ __forceinline__ void fill_pad(char* smem, int dst_off,
                                         const uint4* __restrict__ src,  // 8 fp16 per uint4
                                         long long first_row, int stride_u4, int k0_u4,
                                         int nvalid, int tid) {
    for (int u = tid; u < ROWS * 8; u += 256) {
        int r = u >> 3, c = u & 7;
        uint4 v = make_uint4(0, 0, 0, 0);
        if (r < nvalid) v = src[(size_t)(first_row + r) * stride_u4 + k0_u4 + c];
        *reinterpret_cast<uint4*>(smem + dst_off + r * 144 + c * 16) = v;
    }
}

// fp32 source -> fp16 hi/lo tiles (v = hi + lo, residual exact to ~2^-22); ROWS x 64 cols
template <int ROWS>
__device__ __forceinline__ void fill_split(char* smem, int hi_off, int lo_off,
                                           const float4* __restrict__ src,  // 4 fp32 per float4
                                           long long first_row, int stride_f4, int k0_f4,
                                           int nvalid, int tid) {
    for (int u = tid; u < ROWS * 16; u += 256) {
        int r = u >> 4, c = u & 15;
        float4 v = make_float4(0, 0, 0, 0);
        if (r < nvalid) v = src[(size_t)(first_row + r) * stride_f4 + k0_f4 + c];
        __half hx = __float2half(v.x), hy = __float2half(v.y);
        __half hz = __float2half(v.z), hw = __float2half(v.w);
        uint2 hi2 = make_uint2(hpack(hx, hy), hpack(hz, hw));
        uint2 lo2 = make_uint2(
            hpack(__float2half(v.x - __half2float(hx)), __float2half(v.y - __half2float(hy))),
            hpack(__float2half(v.z - __half2float(hz)), __float2half(v.w - __half2float(hw))));
        int bo = r * 144 + c * 8;
        *reinterpret_cast<uint2*>(smem + hi_off + bo) = hi2;
        *reinterpret_cast<uint2*>(smem + lo_off + bo) = lo2;
    }
}

// ---------------- GEMM1: h1[M,128] (fp16) = x[M,256] @ W1, fp16x2 A x fp16 B ----------------
static constexpr int G1_SMEM = 3 * 18432;   // Ahi/Alo/B, 128 rows x 144B
__global__ void __launch_bounds__(256) k_gemm1_tc(const float* __restrict__ x, int M) {
    extern __shared__ char smem[];
    uint32_t sb = smem_to_u32(smem);
    const int tid = threadIdx.x, wid = tid >> 5, lane = tid & 31;
    const int warpM = wid & 3, warpN = wid >> 2;          // 4 x 2 warps
    const int AHI = 0, ALO = 18432, BT = 36864;

    long long row0 = (long long)blockIdx.x * 128;
    int nvalid = (int)((M - row0 < 128) ? (M - row0) : 128);
    const float4* x4 = reinterpret_cast<const float4*>(x);
    const uint4* w4 = reinterpret_cast<const uint4*>(g_w1);

    float acc[2][8][4];
    #pragma unroll
    for (int i = 0; i < 2; i++)
        #pragma unroll
        for (int j = 0; j < 8; j++)
            #pragma unroll
            for (int k = 0; k < 4; k++) acc[i][j][k] = 0.0f;

    const int a_r = (lane & 7) + ((lane & 8) ? 8 : 0);
    const int a_c = (lane & 16) ? 8 : 0;
    const int b_r = (lane & 7) + ((lane & 16) ? 8 : 0);
    const int b_c = (lane & 8) ? 8 : 0;

    #pragma unroll 1
    for (int c = 0; c < 4; c++) {                         // K chunks of 64 (K=256)
        if (c) __syncthreads();
        fill_split<128>(smem, AHI, ALO, x4, row0, 64, c * 16, nvalid, tid);
        fill_pad<128>(smem, BT, w4, 0, 32, c * 8, 128, tid);
        __syncthreads();
        #pragma unroll
        for (int k16 = 0; k16 < 4; k16++) {
            int kc = k16 * 16;
            uint32_t ah[2][4], al[2][4];
            #pragma unroll
            for (int mt = 0; mt < 2; mt++) {
                uint32_t off = (uint32_t)((warpM * 32 + mt * 16 + a_r) * 144 + (kc + a_c) * 2);
                ldmx4(ah[mt], sb + AHI + off);
                ldmx4(al[mt], sb + ALO + off);
            }
            uint32_t bt[8][2];
            #pragma unroll
            for (int np = 0; np < 4; np++) {
                uint32_t off = (uint32_t)((warpN * 64 + np * 16 + b_r) * 144 + (kc + b_c) * 2);
                uint32_t t4[4];
                ldmx4(t4, sb + BT + off);
                bt[2*np][0] = t4[0]; bt[2*np][1] = t4[1];
                bt[2*np+1][0] = t4[2]; bt[2*np+1][1] = t4[3];
            }
            #pragma unroll
            for (int mt = 0; mt < 2; mt++)
                #pragma unroll
                for (int nt = 0; nt < 8; nt++) {
                    mma16816h(acc[mt][nt], ah[mt], bt[nt]);
                    mma16816h(acc[mt][nt], al[mt], bt[nt]);
                }
        }
    }
    int g = lane >> 2, t = lane & 3;
    #pragma unroll
    for (int mt = 0; mt < 2; mt++) {
        long long r0 = row0 + warpM * 32 + mt * 16 + g;
        #pragma unroll
        for (int nt = 0; nt < 8; nt++) {
            int col = warpN * 64 + nt * 8 + t * 2;
            if (r0 < M)
                *reinterpret_cast<__half2*>(&g_h1[r0 * HDIM + col]) =
                    __floats2half2_rn(acc[mt][nt][0], acc[mt][nt][1]);
            if (r0 + 8 < M)
                *reinterpret_cast<__half2*>(&g_h1[(r0 + 8) * HDIM + col]) =
                    __floats2half2_rn(acc[mt][nt][2], acc[mt][nt][3]);
        }
    }
}

// ---------------- GEMM2: h2 fp16 interleaved = {g1,p1}(fp16, exact) @ W2(fp16) -------------
static constexpr int G2_SMEM = 18432 + 9216;   // A + B
__global__ void __launch_bounds__(256) k_gemm2_tc(int M) {
    extern __shared__ char smem[];
    uint32_t sb = smem_to_u32(smem);
    const int tid = threadIdx.x, wid = tid >> 5, lane = tid & 31;
    const int warpM = wid & 3, warpN = wid >> 2;          // 4 x 2 warps, warp tile 32x32
    const int AT = 0, BT = 18432;

    long long row0 = (long long)blockIdx.x * 128;
    int nvalid = (int)((M - row0 < 128) ? (M - row0) : 128);
    const uint4* a4 = reinterpret_cast<const uint4*>(blockIdx.y ? g_p1 : g_g1);  // 8 fp16/uint4
    const uint4* w4 = reinterpret_cast<const uint4*>(g_w2);
    const int cbase = blockIdx.y * ODIM;

    float acc[2][4][4];
    #pragma unroll
    for (int i = 0; i < 2; i++)
        #pragma unroll
        for (int j = 0; j < 4; j++)
            #pragma unroll
            for (int k = 0; k < 4; k++) acc[i][j][k] = 0.0f;

    const int a_r = (lane & 7) + ((lane & 8) ? 8 : 0);
    const int a_c = (lane & 16) ? 8 : 0;
    const int b_r = (lane & 7) + ((lane & 16) ? 8 : 0);
    const int b_c = (lane & 8) ? 8 : 0;

    #pragma unroll 1
    for (int c = 0; c < 2; c++) {                         // K chunks of 64 (K=128)
        if (c) __syncthreads();
        fill_pad<128>(smem, AT, a4, row0, 16, c * 8, nvalid, tid);
        fill_pad<64>(smem, BT, w4, 0, 16, c * 8, 64, tid);
        __syncthreads();
        #pragma unroll
        for (int k16 = 0; k16 < 4; k16++) {
            int kc = k16 * 16;
            uint32_t at[2][4];
            #pragma unroll
            for (int mt = 0; mt < 2; mt++) {
                uint32_t off = (uint32_t)((warpM * 32 + mt * 16 + a_r) * 144 + (kc + a_c) * 2);
                ldmx4(at[mt], sb + AT + off);
            }
            uint32_t bt[4][2];
            #pragma unroll
            for (int np = 0; np < 2; np++) {
                uint32_t off = (uint32_t)((warpN * 32 + np * 16 + b_r) * 144 + (kc + b_c) * 2);
                uint32_t t4[4];
                ldmx4(t4, sb + BT + off);
                bt[2*np][0] = t4[0]; bt[2*np][1] = t4[1];
                bt[2*np+1][0] = t4[2]; bt[2*np+1][1] = t4[3];
            }
            #pragma unroll
            for (int mt = 0; mt < 2; mt++)
                #pragma unroll
                for (int nt = 0; nt < 4; nt++)
                    mma16816h(acc[mt][nt], at[mt], bt[nt]);
        }
    }
    int g = lane >> 2, t = lane & 3;
    #pragma unroll
    for (int mt = 0; mt < 2; mt++) {
        long long r0 = row0 + warpM * 32 + mt * 16 + g;
        #pragma unroll
        for (int nt = 0; nt < 4; nt++) {
            int col = cbase + warpN * 32 + nt * 8 + t * 2;
            if (r0 < M)
                *reinterpret_cast<__half2*>(&g_h2[r0 * 2 * ODIM + col]) =
                    __floats2half2_rn(acc[mt][nt][0], acc[mt][nt][1]);
            if (r0 + 8 < M)
                *reinterpret_cast<__half2*>(&g_h2[(r0 + 8) * 2 * ODIM + col]) =
                    __floats2half2_rn(acc[mt][nt][2], acc[mt][nt][3]);
        }
    }
}

// ---------------- layer-1 aggregation: warp/node, fp16 gather, fp16 out ----------------
__device__ __forceinline__ float4 h1load(size_t node, int lane) {
    uint2 u = *reinterpret_cast<const uint2*>(&g_h1[node * HDIM + lane * 4]);
    float2 f01 = __half22float2(*reinterpret_cast<__half2*>(&u.x));
    float2 f23 = __half22float2(*reinterpret_cast<__half2*>(&u.y));
    return make_float4(f01.x, f01.y, f23.x, f23.y);
}

__global__ void k_agg1(const float* __restrict__ b1, int n) {
    int node = (blockIdx.x * blockDim.x + threadIdx.x) >> 5;
    int lane = threadIdx.x & 31;
    if (node >= n) return;
    int s0 = g_colptr[node], s1 = g_colptr[node + 1];
    float4 ag = make_float4(0, 0, 0, 0);
    float4 ap = make_float4(0, 0, 0, 0);
    int e = s0;
    for (; e + 1 < s1; e += 2) {
        int sA = g_src[e], sB = g_src[e + 1];
        float gnA = g_gn[e], pnA = g_pn[e];
        float gnB = g_gn[e + 1], pnB = g_pn[e + 1];
        float4 vA = h1load((size_t)sA, lane);
        float4 vB = h1load((size_t)sB, lane);
        ag.x += gnA * vA.x + gnB * vB.x; ag.y += gnA * vA.y + gnB * vB.y;
        ag.z += gnA * vA.z + gnB * vB.z; ag.w += gnA * vA.w + gnB * vB.w;
        ap.x += pnA * vA.x + pnB * vB.x; ap.y += pnA * vA.y + pnB * vB.y;
        ap.z += pnA * vA.z + pnB * vB.z; ap.w += pnA * vA.w + pnB * vB.w;
    }
    if (e < s1) {
        int s = g_src[e];
        float gn = g_gn[e], pn = g_pn[e];
        float4 v = h1load((size_t)s, lane);
        ag.x += gn * v.x; ag.y += gn * v.y; ag.z += gn * v.z; ag.w += gn * v.w;
        ap.x += pn * v.x; ap.y += pn * v.y; ap.z += pn * v.z; ap.w += pn * v.w;
    }
    float dg = g_disg[node]; dg *= dg;
    float dp = g_disp[node]; dp *= dp;
    float4 v = h1load((size_t)node, lane);
    ag.x += dg * v.x; ag.y += dg * v.y; ag.z += dg * v.z; ag.w += dg * v.w;
    ap.x += dp * v.x; ap.y += dp * v.y; ap.z += dp * v.z; ap.w += dp * v.w;
    float4 bb = *reinterpret_cast<const float4*>(&b1[lane * 4]);
    ag.x = fmaxf(ag.x + bb.x, 0.f); ag.y = fmaxf(ag.y + bb.y, 0.f);
    ag.z = fmaxf(ag.z + bb.z, 0.f); ag.w = fmaxf(ag.w + bb.w, 0.f);
    ap.x = fmaxf(ap.x + bb.x, 0.f); ap.y = fmaxf(ap.y + bb.y, 0.f);
    ap.z = fmaxf(ap.z + bb.z, 0.f); ap.w = fmaxf(ap.w + bb.w, 0.f);
    size_t base = (size_t)node * HDIM + lane * 4;
    __half2* gdst = reinterpret_cast<__half2*>(&g_g1[base]);
    gdst[0] = __floats2half2_rn(ag.x, ag.y);
    gdst[1] = __floats2half2_rn(ag.z, ag.w);
    __half2* pdst = reinterpret_cast<__half2*>(&g_p1[base]);
    pdst[0] = __floats2half2_rn(ap.x, ap.y);
    pdst[1] = __floats2half2_rn(ap.z, ap.w);
}

// ---------------- layer-2 aggregation (fp16 gather) + attention combine ----------------
// lanes 0-15: GCN branch (h2 cols 0-63), lanes 16-31: PPMI branch (cols 64-127)
__device__ __forceinline__ void h2gather(size_t node, int lane, float4& a, float w) {
    uint2 u = *reinterpret_cast<const uint2*>(&g_h2[node * 2 * ODIM + lane * 4]);
    float2 f01 = __half22float2(*reinterpret_cast<__half2*>(&u.x));
    float2 f23 = __half22float2(*reinterpret_cast<__half2*>(&u.y));
    a.x += w * f01.x; a.y += w * f01.y; a.z += w * f23.x; a.w += w * f23.y;
}

__global__ void k_agg2_combine(const float* __restrict__ b2,
                               const float* __restrict__ dw,
                               const float* __restrict__ db,
                               float* __restrict__ out, int n) {
    int node = (blockIdx.x * blockDim.x + threadIdx.x) >> 5;
    int lane = threadIdx.x & 31;
    if (node >= n) return;
    int s0 = g_colptr[node], s1 = g_colptr[node + 1];
    const bool isg = lane < 16;
    float4 a = make_float4(0, 0, 0, 0);
    int e = s0;
    for (; e + 1 < s1; e += 2) {
        int sA = g_src[e], sB = g_src[e + 1];
        float wA = isg ? g_gn[e] : g_pn[e];
        float wB = isg ? g_gn[e + 1] : g_pn[e + 1];
        h2gather((size_t)sA, lane, a, wA);
        h2gather((size_t)sB, lane, a, wB);
    }
    if (e < s1) {
        int s = g_src[e];
        h2gather((size_t)s, lane, a, isg ? g_gn[e] : g_pn[e]);
    }
    float d = isg ? g_disg[node] : g_disp[node];
    d *= d;
    h2gather((size_t)node, lane, a, d);
    int c4 = (lane & 15) * 4;
    float4 bb = *reinterpret_cast<const float4*>(&b2[c4]);
    a.x += bb.x; a.y += bb.y; a.z += bb.z; a.w += bb.w;
    // per-branch logits via masked full-warp reduction
    float4 w4 = *reinterpret_cast<const float4*>(&dw[c4]);
    float dot = a.x * w4.x + a.y * w4.y + a.z * w4.z + a.w * w4.w;
    float pg = isg ? dot : 0.0f;
    float pp = isg ? 0.0f : dot;
    #pragma unroll
    for (int o = 16; o; o >>= 1) {
        pg += __shfl_xor_sync(0xffffffffu, pg, o);
        pp += __shfl_xor_sync(0xffffffffu, pp, o);
    }
    float bd = db[0];
    float lg = pg + bd, lp = pp + bd;
    float m = fmaxf(lg, lp);
    float eg = __expf(lg - m), ep = __expf(lp - m);
    float wg = eg / (eg + ep), wp = 1.0f - wg;
    float4 o4;
    o4.x = __shfl_xor_sync(0xffffffffu, a.x, 16);
    o4.y = __shfl_xor_sync(0xffffffffu, a.y, 16);
    o4.z = __shfl_xor_sync(0xffffffffu, a.z, 16);
    o4.w = __shfl_xor_sync(0xffffffffu, a.w, 16);
    if (isg) {
        float4 r;
        r.x = wg * a.x + wp * o4.x; r.y = wg * a.y + wp * o4.y;
        r.z = wg * a.z + wp * o4.z; r.w = wg * a.w + wp * o4.w;
        *reinterpret_cast<float4*>(&out[(size_t)node * ODIM + c4]) = r;
    }
}

// ---------------- launch ----------------
extern "C" void kernel_launch(void* const* d_in, const int* in_sizes, int n_in,
                              void* d_out, int out_size) {
    const float* x    = (const float*)d_in[0];
    const int*   ei   = (const int*)d_in[1];     // int32 [2, E]
    const float* ppmi = (const float*)d_in[2];
    const float* W1   = (const float*)d_in[3];
    const float* b1   = (const float*)d_in[4];
    const float* W2   = (const float*)d_in[5];
    const float* b2   = (const float*)d_in[6];
    const float* dw   = (const float*)d_in[7];
    const float* db   = (const float*)d_in[8];
    float*       out  = (float*)d_out;

    const int N = in_sizes[0] / DDIM;
    const int E = in_sizes[2];

    cudaFuncSetAttribute(k_gemm1_tc, cudaFuncAttributeMaxDynamicSharedMemorySize, G1_SMEM);
    cudaFuncSetAttribute(k_gemm2_tc, cudaFuncAttributeMaxDynamicSharedMemorySize, G2_SMEM);

    const int TB = 256;
    const bool fork = (g_s2 != nullptr) && (g_ev0 != nullptr) && (g_ev1 != nullptr);
    cudaStream_t sb = fork ? g_s2 : (cudaStream_t)0;

    // --- branch A (side stream): CSR graph build ---
    if (fork) {
        cudaEventRecord(g_ev0, 0);
        cudaStreamWaitEvent(g_s2, g_ev0, 0);
    }
    k_init<<<(N + TB - 1) / TB, TB, 0, sb>>>(N);
    k_deg<<<(E + TB - 1) / TB, TB, 0, sb>>>(ei, ppmi, E);
    k_rsqrt<<<(N + TB - 1) / TB, TB, 0, sb>>>(N);
    int nb = (N + 1023) / 1024;
    k_scan1<<<nb, 1024, 0, sb>>>(N);
    k_scan2<<<1, 128, 0, sb>>>(nb);
    k_scan3<<<nb, 1024, 0, sb>>>(N, E);
    k_fill<<<(E + TB - 1) / TB, TB, 0, sb>>>(ei, ppmi, E);
    if (fork) cudaEventRecord(g_ev1, g_s2);

    // --- branch B (capture stream): weight prep + GEMM1 ---
    k_splitW<<<(DDIM * HDIM + HDIM * ODIM + TB - 1) / TB, TB>>>(W1, W2);
    int g1 = (N + 127) / 128;
    k_gemm1_tc<<<g1, 256, G1_SMEM>>>(x, N);

    // --- join, then serial tail ---
    if (fork) cudaStreamWaitEvent((cudaStream_t)0, g_ev1, 0);
    k_agg1<<<(N * 32 + TB - 1) / TB, TB>>>(b1, N);
    dim3 grid2(g1, 2);
    k_gemm2_tc<<<grid2, 256, G2_SMEM>>>(N);
    k_agg2_combine<<<(N * 32 + TB - 1) / TB, TB>>>(b2, dw, db, out, N);
}

// round 16
// speedup vs baseline: 1.7498x; 1.0301x over previous
#include <cuda_runtime.h>
#include <cuda_bf16.h>
#include <cuda_fp16.h>
#include <cstdint>

// Problem-fixed dimensions (N=100000, E=1600000, D=256, H=128, O=64)
#define NMAX 100000
#define EMAX 1600000
#define DDIM 256
#define HDIM 128
#define ODIM 64

// ============================ warp-MMA helpers (plain sm_103 PTX) ============================
__device__ __forceinline__ uint32_t smem_to_u32(const void* p) {
    uint32_t a;
    asm("{ .reg .u64 t; cvta.to.shared.u64 t, %1; cvt.u32.u64 %0, t; }" : "=r"(a) : "l"(p));
    return a;
}
__device__ __forceinline__ void ldmx4(uint32_t* r, uint32_t addr) {
    asm volatile("ldmatrix.sync.aligned.m8n8.x4.shared.b16 {%0,%1,%2,%3}, [%4];"
        : "=r"(r[0]), "=r"(r[1]), "=r"(r[2]), "=r"(r[3]) : "r"(addr));
}
// fp16 x fp16 -> fp32 accumulate
__device__ __forceinline__ void mma16816h(float* d, const uint32_t* a, const uint32_t* b) {
    asm volatile("mma.sync.aligned.m16n8k16.row.col.f32.f16.f16.f32 "
        "{%0,%1,%2,%3}, {%4,%5,%6,%7}, {%8,%9}, {%0,%1,%2,%3};"
        : "+f"(d[0]), "+f"(d[1]), "+f"(d[2]), "+f"(d[3])
        : "r"(a[0]), "r"(a[1]), "r"(a[2]), "r"(a[3]), "r"(b[0]), "r"(b[1]));
}
__device__ __forceinline__ uint32_t hpack(__half a, __half b) {
    __half2 t = __halves2half2(a, b);
    return *reinterpret_cast<uint32_t*>(&t);
}

// ---------------- device scratch (static, no allocation) ----------------
__device__ __half g_h1[NMAX*HDIM];                 // x @ W1 (fp16)
__device__ __half g_g1[NMAX*HDIM];                 // relu(agg_gcn(h1)+b1) fp16
__device__ __half g_p1[NMAX*HDIM];                 // relu(agg_ppmi(h1)+b1) fp16
__device__ __half g_h2[NMAX*2*ODIM];               // interleaved fp16: [node][0:64)=g, [64:128)=p
__device__ __half g_w1[HDIM*DDIM];                 // W1^T fp16: [n=128][k=256]
__device__ __half g_w2[ODIM*HDIM];                 // W2^T fp16: [n=64][k=128]
__device__ float g_disg[NMAX];
__device__ float g_disp[NMAX];
__device__ int   g_cnt   [NMAX];
__device__ int   g_cursor[NMAX];
__device__ int   g_colptr[NMAX+1];
__device__ int   g_src[EMAX];
__device__ float g_gn [EMAX];
__device__ float g_pn [EMAX];
__device__ int   g_bsums[128];

// ---------------- static stream/event fork (created at load; falls back to serial) ----------
static cudaStream_t g_s2 = nullptr;
static cudaEvent_t  g_ev0 = nullptr, g_ev1 = nullptr;
namespace {
struct ForkInit {
    ForkInit() {
        if (cudaStreamCreateWithFlags(&g_s2, cudaStreamNonBlocking) != cudaSuccess) g_s2 = nullptr;
        if (cudaEventCreateWithFlags(&g_ev0, cudaEventDisableTiming) != cudaSuccess) g_ev0 = nullptr;
        if (cudaEventCreateWithFlags(&g_ev1, cudaEventDisableTiming) != cudaSuccess) g_ev1 = nullptr;
    }
};
ForkInit g_forkinit;
}

// ---------------- graph build (re-run every replay) ----------------
__global__ void k_init(int n) {
    int i = blockIdx.x * blockDim.x + threadIdx.x;
    if (i < n) { g_cnt[i] = 0; g_cursor[i] = 0; g_disg[i] = 1.0f; g_disp[i] = 1.0f; }
}

__global__ void k_deg(const int* __restrict__ ei, const float* __restrict__ ppmi, int E) {
    int e = blockIdx.x * blockDim.x + threadIdx.x;
    if (e < E) {
        int r = ei[e]; int c = ei[E + e];
        atomicAdd(&g_disg[r], 1.0f);
        atomicAdd(&g_disp[r], ppmi[e]);
        atomicAdd(&g_cnt[c], 1);
    }
}

__global__ void k_rsqrt(int n) {
    int i = blockIdx.x * blockDim.x + threadIdx.x;
    if (i < n) { g_disg[i] = rsqrtf(g_disg[i]); g_disp[i] = rsqrtf(g_disp[i]); }
}

__global__ void k_scan1(int n) {
    __shared__ int wsum[32];
    int i = blockIdx.x * 1024 + threadIdx.x;
    int v = (i < n) ? g_cnt[i] : 0;
    int x = v;
    #pragma unroll
    for (int o = 1; o < 32; o <<= 1) {
        int y = __shfl_up_sync(0xffffffffu, x, o);
        if ((threadIdx.x & 31) >= o) x += y;
    }
    if ((threadIdx.x & 31) == 31) wsum[threadIdx.x >> 5] = x;
    __syncthreads();
    if (threadIdx.x < 32) {
        int s = wsum[threadIdx.x];
        #pragma unroll
        for (int o = 1; o < 32; o <<= 1) {
            int y = __shfl_up_sync(0xffffffffu, s, o);
            if (threadIdx.x >= o) s += y;
        }
        wsum[threadIdx.x] = s;
    }
    __syncthreads();
    int base = (threadIdx.x >= 32) ? wsum[(threadIdx.x >> 5) - 1] : 0;
    int incl = base + x;
    if (i < n) g_colptr[i] = incl - v;
    if (threadIdx.x == 1023) g_bsums[blockIdx.x] = incl;
}

__global__ void k_scan2(int nb) {
    __shared__ int s[128];
    int t = threadIdx.x;
    s[t] = (t < nb) ? g_bsums[t] : 0;
    __syncthreads();
    for (int o = 1; o < 128; o <<= 1) {
        int y = (t >= o) ? s[t - o] : 0;
        __syncthreads();
        s[t] += y;
        __syncthreads();
    }
    if (t < nb) g_bsums[t] = (t > 0) ? s[t - 1] : 0;
}

__global__ void k_scan3(int n, int E) {
    int i = blockIdx.x * 1024 + threadIdx.x;
    if (i < n) g_colptr[i] += g_bsums[blockIdx.x];
    if (i == 0) g_colptr[n] = E;
}

__global__ void k_fill(const int* __restrict__ ei, const float* __restrict__ ppmi, int E) {
    int e = blockIdx.x * blockDim.x + threadIdx.x;
    if (e >= E) return;
    int r = ei[e]; int c = ei[E + e];
    int pos = g_colptr[c] + atomicAdd(&g_cursor[c], 1);
    g_src[pos] = r;
    g_gn[pos] = g_disg[r] * g_disg[c];
    g_pn[pos] = g_disp[r] * ppmi[e] * g_disp[c];
}

// ---------------- weight prep: transpose to [n][k] fp16, one launch ----------------
__global__ void k_splitW(const float* __restrict__ W1, const float* __restrict__ W2) {
    int i = blockIdx.x * blockDim.x + threadIdx.x;
    if (i < DDIM * HDIM) {                       // W1 [256,128] -> T fp16 [128][256]
        int k = i >> 7, nn = i & 127;
        g_w1[nn * DDIM + k] = __float2half(W1[k * HDIM + nn]);
    } else if (i < DDIM * HDIM + HDIM * ODIM) {  // W2 [128,64] -> T fp16 [64][128]
        int j = i - DDIM * HDIM;
        int k = j >> 6, nn = j & 63;
        g_w2[nn * HDIM + k] = __float2half(W2[k * ODIM + nn]);
    }
}

// ---------------- SMEM tile fill: ROWS x 64 halfwords, padded row stride 144 B ----------------
template <int ROWS>
__device__ __forceinline__ void fill_pad(char* smem, int dst_off,
                                         const uint4* __restrict__ src,  // 8 fp16 per uint4
                                         long long first_row, int stride_u4, int k0_u4,
                                         int nvalid, int tid) {
    for (int u = tid; u < ROWS * 8; u += 256) {
        int r = u >> 3, c = u & 7;
        uint4 v = make_uint4(0, 0, 0, 0);
        if (r < nvalid) v = src[(size_t)(first_row + r) * stride_u4 + k0_u4 + c];
        *reinterpret_cast<uint4*>(smem + dst_off + r * 144 + c * 16) = v;
    }
}

// fp32 source -> single fp16 tile; ROWS x 64 cols
template <int ROWS>
__device__ __forceinline__ void fill_cvt(char* smem, int dst_off,
                                         const float4* __restrict__ src,  // 4 fp32 per float4
                                         long long first_row, int stride_f4, int k0_f4,
                                         int nvalid, int tid) {
    for (int u = tid; u < ROWS * 16; u += 256) {
        int r = u >> 4, c = u & 15;
        float4 v = make_float4(0, 0, 0, 0);
        if (r < nvalid) v = src[(size_t)(first_row + r) * stride_f4 + k0_f4 + c];
        uint2 h2 = make_uint2(hpack(__float2half(v.x), __float2half(v.y)),
                              hpack(__float2half(v.z), __float2half(v.w)));
        *reinterpret_cast<uint2*>(smem + dst_off + r * 144 + c * 8) = h2;
    }
}

// ---------------- GEMM1: h1[M,128] (fp16) = x[M,256] @ W1, single fp16 MMA ----------------
static constexpr int G1_SMEM = 2 * 18432;   // A/B, 128 rows x 144B
__global__ void __launch_bounds__(256) k_gemm1_tc(const float* __restrict__ x, int M) {
    extern __shared__ char smem[];
    uint32_t sb = smem_to_u32(smem);
    const int tid = threadIdx.x, wid = tid >> 5, lane = tid & 31;
    const int warpM = wid & 3, warpN = wid >> 2;          // 4 x 2 warps
    const int AT = 0, BT = 18432;

    long long row0 = (long long)blockIdx.x * 128;
    int nvalid = (int)((M - row0 < 128) ? (M - row0) : 128);
    const float4* x4 = reinterpret_cast<const float4*>(x);
    const uint4* w4 = reinterpret_cast<const uint4*>(g_w1);

    float acc[2][8][4];
    #pragma unroll
    for (int i = 0; i < 2; i++)
        #pragma unroll
        for (int j = 0; j < 8; j++)
            #pragma unroll
            for (int k = 0; k < 4; k++) acc[i][j][k] = 0.0f;

    const int a_r = (lane & 7) + ((lane & 8) ? 8 : 0);
    const int a_c = (lane & 16) ? 8 : 0;
    const int b_r = (lane & 7) + ((lane & 16) ? 8 : 0);
    const int b_c = (lane & 8) ? 8 : 0;

    #pragma unroll 1
    for (int c = 0; c < 4; c++) {                         // K chunks of 64 (K=256)
        if (c) __syncthreads();
        fill_cvt<128>(smem, AT, x4, row0, 64, c * 16, nvalid, tid);
        fill_pad<128>(smem, BT, w4, 0, 32, c * 8, 128, tid);
        __syncthreads();
        #pragma unroll
        for (int k16 = 0; k16 < 4; k16++) {
            int kc = k16 * 16;
            uint32_t at[2][4];
            #pragma unroll
            for (int mt = 0; mt < 2; mt++) {
                uint32_t off = (uint32_t)((warpM * 32 + mt * 16 + a_r) * 144 + (kc + a_c) * 2);
                ldmx4(at[mt], sb + AT + off);
            }
            uint32_t bt[8][2];
            #pragma unroll
            for (int np = 0; np < 4; np++) {
                uint32_t off = (uint32_t)((warpN * 64 + np * 16 + b_r) * 144 + (kc + b_c) * 2);
                uint32_t t4[4];
                ldmx4(t4, sb + BT + off);
                bt[2*np][0] = t4[0]; bt[2*np][1] = t4[1];
                bt[2*np+1][0] = t4[2]; bt[2*np+1][1] = t4[3];
            }
            #pragma unroll
            for (int mt = 0; mt < 2; mt++)
                #pragma unroll
                for (int nt = 0; nt < 8; nt++)
                    mma16816h(acc[mt][nt], at[mt], bt[nt]);
        }
    }
    int g = lane >> 2, t = lane & 3;
    #pragma unroll
    for (int mt = 0; mt < 2; mt++) {
        long long r0 = row0 + warpM * 32 + mt * 16 + g;
        #pragma unroll
        for (int nt = 0; nt < 8; nt++) {
            int col = warpN * 64 + nt * 8 + t * 2;
            if (r0 < M)
                *reinterpret_cast<__half2*>(&g_h1[r0 * HDIM + col]) =
                    __floats2half2_rn(acc[mt][nt][0], acc[mt][nt][1]);
            if (r0 + 8 < M)
                *reinterpret_cast<__half2*>(&g_h1[(r0 + 8) * HDIM + col]) =
                    __floats2half2_rn(acc[mt][nt][2], acc[mt][nt][3]);
        }
    }
}

// ---------------- GEMM2: h2 fp16 interleaved = {g1,p1}(fp16) @ W2(fp16) -------------
static constexpr int G2_SMEM = 18432 + 9216;   // A + B
__global__ void __launch_bounds__(256) k_gemm2_tc(int M) {
    extern __shared__ char smem[];
    uint32_t sb = smem_to_u32(smem);
    const int tid = threadIdx.x, wid = tid >> 5, lane = tid & 31;
    const int warpM = wid & 3, warpN = wid >> 2;          // 4 x 2 warps, warp tile 32x32
    const int AT = 0, BT = 18432;

    long long row0 = (long long)blockIdx.x * 128;
    int nvalid = (int)((M - row0 < 128) ? (M - row0) : 128);
    const uint4* a4 = reinterpret_cast<const uint4*>(blockIdx.y ? g_p1 : g_g1);  // 8 fp16/uint4
    const uint4* w4 = reinterpret_cast<const uint4*>(g_w2);
    const int cbase = blockIdx.y * ODIM;

    float acc[2][4][4];
    #pragma unroll
    for (int i = 0; i < 2; i++)
        #pragma unroll
        for (int j = 0; j < 4; j++)
            #pragma unroll
            for (int k = 0; k < 4; k++) acc[i][j][k] = 0.0f;

    const int a_r = (lane & 7) + ((lane & 8) ? 8 : 0);
    const int a_c = (lane & 16) ? 8 : 0;
    const int b_r = (lane & 7) + ((lane & 16) ? 8 : 0);
    const int b_c = (lane & 8) ? 8 : 0;

    #pragma unroll 1
    for (int c = 0; c < 2; c++) {                         // K chunks of 64 (K=128)
        if (c) __syncthreads();
        fill_pad<128>(smem, AT, a4, row0, 16, c * 8, nvalid, tid);
        fill_pad<64>(smem, BT, w4, 0, 16, c * 8, 64, tid);
        __syncthreads();
        #pragma unroll
        for (int k16 = 0; k16 < 4; k16++) {
            int kc = k16 * 16;
            uint32_t at[2][4];
            #pragma unroll
            for (int mt = 0; mt < 2; mt++) {
                uint32_t off = (uint32_t)((warpM * 32 + mt * 16 + a_r) * 144 + (kc + a_c) * 2);
                ldmx4(at[mt], sb + AT + off);
            }
            uint32_t bt[4][2];
            #pragma unroll
            for (int np = 0; np < 2; np++) {
                uint32_t off = (uint32_t)((warpN * 32 + np * 16 + b_r) * 144 + (kc + b_c) * 2);
                uint32_t t4[4];
                ldmx4(t4, sb + BT + off);
                bt[2*np][0] = t4[0]; bt[2*np][1] = t4[1];
                bt[2*np+1][0] = t4[2]; bt[2*np+1][1] = t4[3];
            }
            #pragma unroll
            for (int mt = 0; mt < 2; mt++)
                #pragma unroll
                for (int nt = 0; nt < 4; nt++)
                    mma16816h(acc[mt][nt], at[mt], bt[nt]);
        }
    }
    int g = lane >> 2, t = lane & 3;
    #pragma unroll
    for (int mt = 0; mt < 2; mt++) {
        long long r0 = row0 + warpM * 32 + mt * 16 + g;
        #pragma unroll
        for (int nt = 0; nt < 4; nt++) {
            int col = cbase + warpN * 32 + nt * 8 + t * 2;
            if (r0 < M)
                *reinterpret_cast<__half2*>(&g_h2[r0 * 2 * ODIM + col]) =
                    __floats2half2_rn(acc[mt][nt][0], acc[mt][nt][1]);
            if (r0 + 8 < M)
                *reinterpret_cast<__half2*>(&g_h2[(r0 + 8) * 2 * ODIM + col]) =
                    __floats2half2_rn(acc[mt][nt][2], acc[mt][nt][3]);
        }
    }
}

// ---------------- layer-1 aggregation: warp/node, fp16 gather, fp16 out ----------------
__device__ __forceinline__ float4 h1load(size_t node, int lane) {
    uint2 u = *reinterpret_cast<const uint2*>(&g_h1[node * HDIM + lane * 4]);
    float2 f01 = __half22float2(*reinterpret_cast<__half2*>(&u.x));
    float2 f23 = __half22float2(*reinterpret_cast<__half2*>(&u.y));
    return make_float4(f01.x, f01.y, f23.x, f23.y);
}

__global__ void k_agg1(const float* __restrict__ b1, int n) {
    int node = (blockIdx.x * blockDim.x + threadIdx.x) >> 5;
    int lane = threadIdx.x & 31;
    if (node >= n) return;
    int s0 = g_colptr[node], s1 = g_colptr[node + 1];
    float4 ag = make_float4(0, 0, 0, 0);
    float4 ap = make_float4(0, 0, 0, 0);
    int e = s0;
    for (; e + 1 < s1; e += 2) {
        int sA = g_src[e], sB = g_src[e + 1];
        float gnA = g_gn[e], pnA = g_pn[e];
        float gnB = g_gn[e + 1], pnB = g_pn[e + 1];
        float4 vA = h1load((size_t)sA, lane);
        float4 vB = h1load((size_t)sB, lane);
        ag.x += gnA * vA.x + gnB * vB.x; ag.y += gnA * vA.y + gnB * vB.y;
        ag.z += gnA * vA.z + gnB * vB.z; ag.w += gnA * vA.w + gnB * vB.w;
        ap.x += pnA * vA.x + pnB * vB.x; ap.y += pnA * vA.y + pnB * vB.y;
        ap.z += pnA * vA.z + pnB * vB.z; ap.w += pnA * vA.w + pnB * vB.w;
    }
    if (e < s1) {
        int s = g_src[e];
        float gn = g_gn[e], pn = g_pn[e];
        float4 v = h1load((size_t)s, lane);
        ag.x += gn * v.x; ag.y += gn * v.y; ag.z += gn * v.z; ag.w += gn * v.w;
        ap.x += pn * v.x; ap.y += pn * v.y; ap.z += pn * v.z; ap.w += pn * v.w;
    }
    float dg = g_disg[node]; dg *= dg;
    float dp = g_disp[node]; dp *= dp;
    float4 v = h1load((size_t)node, lane);
    ag.x += dg * v.x; ag.y += dg * v.y; ag.z += dg * v.z; ag.w += dg * v.w;
    ap.x += dp * v.x; ap.y += dp * v.y; ap.z += dp * v.z; ap.w += dp * v.w;
    float4 bb = *reinterpret_cast<const float4*>(&b1[lane * 4]);
    ag.x = fmaxf(ag.x + bb.x, 0.f); ag.y = fmaxf(ag.y + bb.y, 0.f);
    ag.z = fmaxf(ag.z + bb.z, 0.f); ag.w = fmaxf(ag.w + bb.w, 0.f);
    ap.x = fmaxf(ap.x + bb.x, 0.f); ap.y = fmaxf(ap.y + bb.y, 0.f);
    ap.z = fmaxf(ap.z + bb.z, 0.f); ap.w = fmaxf(ap.w + bb.w, 0.f);
    size_t base = (size_t)node * HDIM + lane * 4;
    __half2* gdst = reinterpret_cast<__half2*>(&g_g1[base]);
    gdst[0] = __floats2half2_rn(ag.x, ag.y);
    gdst[1] = __floats2half2_rn(ag.z, ag.w);
    __half2* pdst = reinterpret_cast<__half2*>(&g_p1[base]);
    pdst[0] = __floats2half2_rn(ap.x, ap.y);
    pdst[1] = __floats2half2_rn(ap.z, ap.w);
}

// ---------------- layer-2 aggregation (fp16 gather) + attention combine ----------------
// lanes 0-15: GCN branch (h2 cols 0-63), lanes 16-31: PPMI branch (cols 64-127)
__device__ __forceinline__ void h2gather(size_t node, int lane, float4& a, float w) {
    uint2 u = *reinterpret_cast<const uint2*>(&g_h2[node * 2 * ODIM + lane * 4]);
    float2 f01 = __half22float2(*reinterpret_cast<__half2*>(&u.x));
    float2 f23 = __half22float2(*reinterpret_cast<__half2*>(&u.y));
    a.x += w * f01.x; a.y += w * f01.y; a.z += w * f23.x; a.w += w * f23.y;
}

__global__ void k_agg2_combine(const float* __restrict__ b2,
                               const float* __restrict__ dw,
                               const float* __restrict__ db,
                               float* __restrict__ out, int n) {
    int node = (blockIdx.x * blockDim.x + threadIdx.x) >> 5;
    int lane = threadIdx.x & 31;
    if (node >= n) return;
    int s0 = g_colptr[node], s1 = g_colptr[node + 1];
    const bool isg = lane < 16;
    float4 a = make_float4(0, 0, 0, 0);
    int e = s0;
    for (; e + 1 < s1; e += 2) {
        int sA = g_src[e], sB = g_src[e + 1];
        float wA = isg ? g_gn[e] : g_pn[e];
        float wB = isg ? g_gn[e + 1] : g_pn[e + 1];
        h2gather((size_t)sA, lane, a, wA);
        h2gather((size_t)sB, lane, a, wB);
    }
    if (e < s1) {
        int s = g_src[e];
        h2gather((size_t)s, lane, a, isg ? g_gn[e] : g_pn[e]);
    }
    float d = isg ? g_disg[node] : g_disp[node];
    d *= d;
    h2gather((size_t)node, lane, a, d);
    int c4 = (lane & 15) * 4;
    float4 bb = *reinterpret_cast<const float4*>(&b2[c4]);
    a.x += bb.x; a.y += bb.y; a.z += bb.z; a.w += bb.w;
    // per-branch logits via masked full-warp reduction
    float4 w4 = *reinterpret_cast<const float4*>(&dw[c4]);
    float dot = a.x * w4.x + a.y * w4.y + a.z * w4.z + a.w * w4.w;
    float pg = isg ? dot : 0.0f;
    float pp = isg ? 0.0f : dot;
    #pragma unroll
    for (int o = 16; o; o >>= 1) {
        pg += __shfl_xor_sync(0xffffffffu, pg, o);
        pp += __shfl_xor_sync(0xffffffffu, pp, o);
    }
    float bd = db[0];
    float lg = pg + bd, lp = pp + bd;
    float m = fmaxf(lg, lp);
    float eg = __expf(lg - m), ep = __expf(lp - m);
    float wg = eg / (eg + ep), wp = 1.0f - wg;
    float4 o4;
    o4.x = __shfl_xor_sync(0xffffffffu, a.x, 16);
    o4.y = __shfl_xor_sync(0xffffffffu, a.y, 16);
    o4.z = __shfl_xor_sync(0xffffffffu, a.z, 16);
    o4.w = __shfl_xor_sync(0xffffffffu, a.w, 16);
    if (isg) {
        float4 r;
        r.x = wg * a.x + wp * o4.x; r.y = wg * a.y + wp * o4.y;
        r.z = wg * a.z + wp * o4.z; r.w = wg * a.w + wp * o4.w;
        *reinterpret_cast<float4*>(&out[(size_t)node * ODIM + c4]) = r;
    }
}

// ---------------- launch ----------------
extern "C" void kernel_launch(void* const* d_in, const int* in_sizes, int n_in,
                              void* d_out, int out_size) {
    const float* x    = (const float*)d_in[0];
    const int*   ei   = (const int*)d_in[1];     // int32 [2, E]
    const float* ppmi = (const float*)d_in[2];
    const float* W1   = (const float*)d_in[3];
    const float* b1   = (const float*)d_in[4];
    const float* W2   = (const float*)d_in[5];
    const float* b2   = (const float*)d_in[6];
    const float* dw   = (const float*)d_in[7];
    const float* db   = (const float*)d_in[8];
    float*       out  = (float*)d_out;

    const int N = in_sizes[0] / DDIM;
    const int E = in_sizes[2];

    cudaFuncSetAttribute(k_gemm1_tc, cudaFuncAttributeMaxDynamicSharedMemorySize, G1_SMEM);
    cudaFuncSetAttribute(k_gemm2_tc, cudaFuncAttributeMaxDynamicSharedMemorySize, G2_SMEM);

    const int TB = 256;
    const bool fork = (g_s2 != nullptr) && (g_ev0 != nullptr) && (g_ev1 != nullptr);
    cudaStream_t sb = fork ? g_s2 : (cudaStream_t)0;

    // --- branch A (side stream): CSR graph build ---
    if (fork) {
        cudaEventRecord(g_ev0, 0);
        cudaStreamWaitEvent(g_s2, g_ev0, 0);
    }
    k_init<<<(N + TB - 1) / TB, TB, 0, sb>>>(N);
    k_deg<<<(E + TB - 1) / TB, TB, 0, sb>>>(ei, ppmi, E);
    k_rsqrt<<<(N + TB - 1) / TB, TB, 0, sb>>>(N);
    int nb = (N + 1023) / 1024;
    k_scan1<<<nb, 1024, 0, sb>>>(N);
    k_scan2<<<1, 128, 0, sb>>>(nb);
    k_scan3<<<nb, 1024, 0, sb>>>(N, E);
    k_fill<<<(E + TB - 1) / TB, TB, 0, sb>>>(ei, ppmi, E);
    if (fork) cudaEventRecord(g_ev1, g_s2);

    // --- branch B (capture stream): weight prep + GEMM1 ---
    k_splitW<<<(DDIM * HDIM + HDIM * ODIM + TB - 1) / TB, TB>>>(W1, W2);
    int g1 = (N + 127) / 128;
    k_gemm1_tc<<<g1, 256, G1_SMEM>>>(x, N);

    // --- join, then serial tail ---
    if (fork) cudaStreamWaitEvent((cudaStream_t)0, g_ev1, 0);
    k_agg1<<<(N * 32 + TB - 1) / TB, TB>>>(b1, N);
    dim3 grid2(g1, 2);
    k_gemm2_tc<<<grid2, 256, G2_SMEM>>>(N);
    k_agg2_combine<<<(N * 32 + TB - 1) / TB, TB>>>(b2, dw, db, out, N);
}